// round 1
// baseline (speedup 1.0000x reference)
#include <cuda_runtime.h>
#include <math.h>
#include <stdint.h>

#define NTOK  16384      // B*T
#define DIM   512
#define NEXP  8
#define BM    128
#define BN    128
#define BK    16
#define TM_TILES (NTOK / BM)   // 128 worst-case row tiles per expert

typedef unsigned long long ull;

// ---------------- static device scratch (no allocations allowed) ------------
__device__ int            g_count[NEXP];
__device__ int            g_tok [NEXP][NTOK];
__device__ float          g_gate[NEXP][NTOK];
__device__ unsigned char  g_slot[NEXP][NTOK];
__device__ float          g_partial[2][NTOK][DIM];   // 64 MB

// ---------------- kernel 0: zero the per-expert counters -------------------
__global__ void init_counts_kernel() {
    if (threadIdx.x < NEXP) g_count[threadIdx.x] = 0;
}

// ---------------- kernel 1: noisy top-k router ------------------------------
// one warp per token; Wr/Wn staged transposed in smem for conflict-free reads
__global__ void __launch_bounds__(256) router_kernel(
    const float* __restrict__ x,   const float* __restrict__ eps,
    const float* __restrict__ Wr,  const float* __restrict__ br,
    const float* __restrict__ Wn,  const float* __restrict__ bn)
{
    __shared__ float sWr[NEXP][DIM];   // [e][d]
    __shared__ float sWn[NEXP][DIM];
    const int tid = threadIdx.x;
    for (int i = tid; i < DIM * NEXP; i += blockDim.x) {
        int d = i >> 3, e = i & 7;
        sWr[e][d] = Wr[i];
        sWn[e][d] = Wn[i];
    }
    __syncthreads();

    const int warp = tid >> 5, lane = tid & 31;
    const int t = blockIdx.x * 8 + warp;   // 8 warps per block

    const float* xr = x + (size_t)t * DIM;
    float xf[16];
#pragma unroll
    for (int i = 0; i < 16; i++) xf[i] = xr[lane + 32 * i];

    float noisy[NEXP];
#pragma unroll
    for (int e = 0; e < NEXP; e++) {
        float ar = 0.f, an = 0.f;
#pragma unroll
        for (int i = 0; i < 16; i++) {
            int d = lane + 32 * i;
            ar = fmaf(xf[i], sWr[e][d], ar);
            an = fmaf(xf[i], sWn[e][d], an);
        }
#pragma unroll
        for (int o = 16; o; o >>= 1) {
            ar += __shfl_xor_sync(0xffffffffu, ar, o);
            an += __shfl_xor_sync(0xffffffffu, an, o);
        }
        float lg = ar + br[e];
        float nl = an + bn[e];
        // stable softplus: max(x,0) + log1p(exp(-|x|))
        float sp = fmaxf(nl, 0.f) + log1pf(expf(-fabsf(nl)));
        noisy[e] = lg + eps[(size_t)t * NEXP + e] * sp;
    }

    if (lane == 0) {
        // top-2, first-index tiebreak (matches lax.top_k)
        int i1 = 0; float v1 = noisy[0];
#pragma unroll
        for (int e = 1; e < NEXP; e++) if (noisy[e] > v1) { v1 = noisy[e]; i1 = e; }
        int i2 = -1; float v2 = -INFINITY;
#pragma unroll
        for (int e = 0; e < NEXP; e++) if (e != i1 && noisy[e] > v2) { v2 = noisy[e]; i2 = e; }
        // softmax over the two kept logits
        float ex = expf(v2 - v1);
        float inv = 1.f / (1.f + ex);
        float g1 = inv, g2 = ex * inv;

        int p1 = atomicAdd(&g_count[i1], 1);
        g_tok[i1][p1] = t; g_gate[i1][p1] = g1; g_slot[i1][p1] = 0;
        int p2 = atomicAdd(&g_count[i2], 1);
        g_tok[i2][p2] = t; g_gate[i2][p2] = g2; g_slot[i2][p2] = 1;
    }
}

// ---------------- kernel 2: grouped expert GEMM (gathered rows) -------------
// grid.x = NEXP * TM_TILES (row tiles, most exit early), grid.y = DIM/BN
// 256 threads, each computes an 8x8 micro-tile; inner loop uses packed
// fma.rn.f32x2 (FFMA2) for 2x fp32 throughput.
__global__ void __launch_bounds__(256, 2) expert_gemm_kernel(
    const float* __restrict__ x, const float* __restrict__ Wk,
    const float* __restrict__ bk)
{
    const int e   = blockIdx.x / TM_TILES;
    const int mt  = blockIdx.x % TM_TILES;
    const int cnt = g_count[e];
    const int m0  = mt * BM;
    if (m0 >= cnt) return;
    const int nb = blockIdx.y * BN;

    __shared__ float As[2][BK][132];   // transposed A, padded row (132 floats)
    __shared__ float Bs[2][BK][BN];
    __shared__ int   sTok[BM];

    const int tid = threadIdx.x;
    if (tid < BM) {
        int m = m0 + tid;
        sTok[tid] = (m < cnt) ? g_tok[e][m] : g_tok[e][m0];  // pad rows: any valid token
    }
    __syncthreads();

    // per-thread global load coords
    const int arow = tid >> 2;          // 0..63 (second load covers +64)
    const int ac4  = tid & 3;           // which float4 along K
    const float* aptr0 = x + (size_t)sTok[arow]      * DIM + ac4 * 4;
    const float* aptr1 = x + (size_t)sTok[arow + 64] * DIM + ac4 * 4;

    const float* Bp = Wk + (size_t)e * (DIM * DIM) + nb;   // B[k][n] = Bp[k*DIM + n]
    const int brow = tid >> 5;          // 0..7 (second load covers +8)
    const int bc   = (tid & 31) * 4;
    const float* bptr0 = Bp + (size_t)brow * DIM + bc;
    const float* bptr1 = bptr0 + 8 * DIM;

    const int ty4 = (tid >> 4) * 4;
    const int tx4 = (tid & 15) * 4;

    // prologue: fetch + store stage 0
    float4 av0 = *(const float4*)(aptr0);
    float4 av1 = *(const float4*)(aptr1);
    float4 bv0 = *(const float4*)(bptr0);
    float4 bv1 = *(const float4*)(bptr1);
    {
        As[0][ac4 * 4 + 0][arow] = av0.x;  As[0][ac4 * 4 + 1][arow] = av0.y;
        As[0][ac4 * 4 + 2][arow] = av0.z;  As[0][ac4 * 4 + 3][arow] = av0.w;
        As[0][ac4 * 4 + 0][arow + 64] = av1.x;  As[0][ac4 * 4 + 1][arow + 64] = av1.y;
        As[0][ac4 * 4 + 2][arow + 64] = av1.z;  As[0][ac4 * 4 + 3][arow + 64] = av1.w;
        *(float4*)&Bs[0][brow][bc]     = bv0;
        *(float4*)&Bs[0][brow + 8][bc] = bv1;
    }
    __syncthreads();

    ull acc[8][4];
#pragma unroll
    for (int i = 0; i < 8; i++)
#pragma unroll
        for (int j = 0; j < 4; j++) acc[i][j] = 0ull;

    int s = 0;
    for (int k0 = BK; k0 <= DIM; k0 += BK) {
        const bool more = (k0 < DIM);
        float4 nav0, nav1, nbv0, nbv1;
        if (more) {
            nav0 = *(const float4*)(aptr0 + k0);
            nav1 = *(const float4*)(aptr1 + k0);
            nbv0 = *(const float4*)(bptr0 + (size_t)k0 * DIM);
            nbv1 = *(const float4*)(bptr1 + (size_t)k0 * DIM);
        }
        // compute on stage s
#pragma unroll
        for (int k = 0; k < BK; k++) {
            float a[8];
            *(float4*)&a[0] = *(const float4*)&As[s][k][ty4];
            *(float4*)&a[4] = *(const float4*)&As[s][k][ty4 + 64];
            ull b[4];
            *(ulonglong2*)&b[0] = *(const ulonglong2*)&Bs[s][k][tx4];
            *(ulonglong2*)&b[2] = *(const ulonglong2*)&Bs[s][k][tx4 + 64];
#pragma unroll
            for (int i = 0; i < 8; i++) {
                ull a2;
                asm("mov.b64 %0, {%1, %1};" : "=l"(a2) : "f"(a[i]));
#pragma unroll
                for (int j = 0; j < 4; j++)
                    asm("fma.rn.f32x2 %0, %1, %2, %0;"
                        : "+l"(acc[i][j]) : "l"(a2), "l"(b[j]));
            }
        }
        if (more) {
            const int ns = s ^ 1;
            As[ns][ac4 * 4 + 0][arow] = nav0.x;  As[ns][ac4 * 4 + 1][arow] = nav0.y;
            As[ns][ac4 * 4 + 2][arow] = nav0.z;  As[ns][ac4 * 4 + 3][arow] = nav0.w;
            As[ns][ac4 * 4 + 0][arow + 64] = nav1.x;  As[ns][ac4 * 4 + 1][arow + 64] = nav1.y;
            As[ns][ac4 * 4 + 2][arow + 64] = nav1.z;  As[ns][ac4 * 4 + 3][arow + 64] = nav1.w;
            *(float4*)&Bs[ns][brow][bc]     = nbv0;
            *(float4*)&Bs[ns][brow + 8][bc] = nbv1;
            __syncthreads();
            s = ns;
        }
    }

    // epilogue: out = gate * (acc + bk), scattered to slot partial buffer
    float bkv[8];
    {
        const float* bkp = bk + (size_t)e * DIM + nb;
        *(float4*)&bkv[0] = *(const float4*)(bkp + tx4);
        *(float4*)&bkv[4] = *(const float4*)(bkp + tx4 + 64);
    }
#pragma unroll
    for (int half = 0; half < 2; half++) {
#pragma unroll
        for (int ii = 0; ii < 4; ii++) {
            const int mrow = half * 64 + ty4 + ii;
            const int m = m0 + mrow;
            if (m < cnt) {
                const int   tok  = sTok[mrow];
                const float gt   = g_gate[e][m];
                const int   slot = g_slot[e][m];
                const int i = half * 4 + ii;
                float v[8];
#pragma unroll
                for (int j = 0; j < 4; j++) {
                    float lo, hi;
                    asm("mov.b64 {%0, %1}, %2;" : "=f"(lo), "=f"(hi) : "l"(acc[i][j]));
                    v[j * 2 + 0] = lo;
                    v[j * 2 + 1] = hi;
                }
                float4 r0, r1;
                r0.x = gt * (v[0] + bkv[0]);  r0.y = gt * (v[1] + bkv[1]);
                r0.z = gt * (v[2] + bkv[2]);  r0.w = gt * (v[3] + bkv[3]);
                r1.x = gt * (v[4] + bkv[4]);  r1.y = gt * (v[5] + bkv[5]);
                r1.z = gt * (v[6] + bkv[6]);  r1.w = gt * (v[7] + bkv[7]);
                float* op = &g_partial[slot][tok][nb];
                *(float4*)(op + tx4)      = r0;
                *(float4*)(op + tx4 + 64) = r1;
            }
        }
    }
}

// ---------------- kernel 3: combine the two expert contributions ------------
__global__ void combine_kernel(float* __restrict__ out) {
    const size_t i = (size_t)blockIdx.x * blockDim.x + threadIdx.x;  // float4 idx
    const float4* p0 = (const float4*)&g_partial[0][0][0];
    const float4* p1 = (const float4*)&g_partial[1][0][0];
    float4 a = p0[i], b = p1[i];
    float4 r;
    r.x = a.x + b.x; r.y = a.y + b.y; r.z = a.z + b.z; r.w = a.w + b.w;
    ((float4*)out)[i] = r;
}

// ---------------- launch --------------------------------------------------
extern "C" void kernel_launch(void* const* d_in, const int* in_sizes, int n_in,
                              void* d_out, int out_size) {
    const float* x   = (const float*)d_in[0];
    const float* eps = (const float*)d_in[1];
    const float* Wr  = (const float*)d_in[2];
    const float* br  = (const float*)d_in[3];
    const float* Wn  = (const float*)d_in[4];
    const float* bn  = (const float*)d_in[5];
    const float* Wk  = (const float*)d_in[6];
    const float* bk  = (const float*)d_in[7];
    float* out = (float*)d_out;

    init_counts_kernel<<<1, 32>>>();
    router_kernel<<<NTOK / 8, 256>>>(x, eps, Wr, br, Wn, bn);
    dim3 ggrid(NEXP * TM_TILES, DIM / BN);
    expert_gemm_kernel<<<ggrid, 256>>>(x, Wk, bk);
    combine_kernel<<<(NTOK * DIM / 4) / 256, 256>>>(out);
}

// round 3
// speedup vs baseline: 1.3152x; 1.3152x over previous
#include <cuda_runtime.h>
#include <cuda_bf16.h>
#include <math.h>
#include <stdint.h>

#define NTOK  16384
#define DIM   512
#define NEXP  8
#define BM    128
#define BN    128
#define BK    32
#define TM_TILES (NTOK / BM)

// ---------------- static device scratch ------------------------------------
__device__ int            g_count[NEXP];
__device__ int            g_tok [NEXP][NTOK];
__device__ float          g_gate[NEXP][NTOK];
__device__ unsigned char  g_slot[NEXP][NTOK];
__device__ float          g_partial[2][NTOK][DIM];             // 64 MB
__device__ __nv_bfloat16  g_x_hi[NTOK * DIM];
__device__ __nv_bfloat16  g_x_lo[NTOK * DIM];
__device__ __nv_bfloat16  g_wk_hi[NEXP * DIM * DIM];           // [e][n][k]
__device__ __nv_bfloat16  g_wk_lo[NEXP * DIM * DIM];

// ---------------- helpers ---------------------------------------------------
__device__ __forceinline__ uint32_t smem_u32(const void* p) {
    uint32_t a;
    asm("{ .reg .u64 t; cvta.to.shared.u64 t, %1; cvt.u32.u64 %0, t; }" : "=r"(a) : "l"(p));
    return a;
}
__device__ __forceinline__ void cp16(uint32_t saddr, const void* g) {
    asm volatile("cp.async.cg.shared.global [%0], [%1], 16;" :: "r"(saddr), "l"(g));
}
__device__ __forceinline__ void cp_commit() { asm volatile("cp.async.commit_group;"); }
template<int N> __device__ __forceinline__ void cp_wait() {
    asm volatile("cp.async.wait_group %0;" :: "n"(N));
}
__device__ __forceinline__ void ldsm4(uint32_t& r0, uint32_t& r1, uint32_t& r2, uint32_t& r3,
                                      uint32_t addr) {
    asm volatile("ldmatrix.sync.aligned.m8n8.x4.shared.b16 {%0,%1,%2,%3}, [%4];"
                 : "=r"(r0), "=r"(r1), "=r"(r2), "=r"(r3) : "r"(addr));
}
__device__ __forceinline__ void mma16816(float* c, const uint32_t* a, const uint32_t* b) {
    asm volatile(
        "mma.sync.aligned.m16n8k16.row.col.f32.bf16.bf16.f32 "
        "{%0,%1,%2,%3}, {%4,%5,%6,%7}, {%8,%9}, {%0,%1,%2,%3};"
        : "+f"(c[0]), "+f"(c[1]), "+f"(c[2]), "+f"(c[3])
        : "r"(a[0]), "r"(a[1]), "r"(a[2]), "r"(a[3]), "r"(b[0]), "r"(b[1]));
}

// ---------------- kernel 0: zero counters ----------------------------------
__global__ void init_counts_kernel() {
    if (threadIdx.x < NEXP) g_count[threadIdx.x] = 0;
}

// ---------------- bf16 hi/lo split ------------------------------------------
__device__ __forceinline__ void cvt2(float a, float b, uint32_t& hi, uint32_t& lo) {
    __nv_bfloat16 ah = __float2bfloat16(a);
    __nv_bfloat16 bh = __float2bfloat16(b);
    __nv_bfloat16 al = __float2bfloat16(a - __bfloat162float(ah));
    __nv_bfloat16 bl = __float2bfloat16(b - __bfloat162float(bh));
    hi = ((uint32_t)__bfloat16_as_ushort(bh) << 16) | (uint32_t)__bfloat16_as_ushort(ah);
    lo = ((uint32_t)__bfloat16_as_ushort(bl) << 16) | (uint32_t)__bfloat16_as_ushort(al);
}

__global__ void convert_x_kernel(const float* __restrict__ x) {
    const size_t i = (size_t)blockIdx.x * blockDim.x + threadIdx.x;
    float4 v = ((const float4*)x)[i];
    uint32_t h0, l0, h1, l1;
    cvt2(v.x, v.y, h0, l0);
    cvt2(v.z, v.w, h1, l1);
    ((uint2*)g_x_hi)[i] = make_uint2(h0, h1);
    ((uint2*)g_x_lo)[i] = make_uint2(l0, l1);
}

__global__ void convert_wk_kernel(const float* __restrict__ Wk) {
    __shared__ float s[64][65];
    const int e = blockIdx.z, kt = blockIdx.y * 64, nt = blockIdx.x * 64;
    const int tid = threadIdx.x;
    const float* src = Wk + ((size_t)e * DIM + kt) * DIM + nt;
#pragma unroll
    for (int j = 0; j < 4; j++) {
        int unit = tid + 256 * j;
        int kr = unit >> 4, nc = (unit & 15) * 4;
        float4 v = *(const float4*)(src + (size_t)kr * DIM + nc);
        s[kr][nc + 0] = v.x; s[kr][nc + 1] = v.y;
        s[kr][nc + 2] = v.z; s[kr][nc + 3] = v.w;
    }
    __syncthreads();
    __nv_bfloat16* dh = g_wk_hi + ((size_t)e * DIM + nt) * DIM + kt;
    __nv_bfloat16* dl = g_wk_lo + ((size_t)e * DIM + nt) * DIM + kt;
#pragma unroll
    for (int j = 0; j < 4; j++) {
        int unit = tid + 256 * j;
        int nr = unit >> 4, kq = (unit & 15) * 4;
        float a = s[kq + 0][nr], b = s[kq + 1][nr];
        float c = s[kq + 2][nr], d = s[kq + 3][nr];
        uint32_t h0, l0, h1, l1;
        cvt2(a, b, h0, l0);
        cvt2(c, d, h1, l1);
        *(uint2*)(dh + (size_t)nr * DIM + kq) = make_uint2(h0, h1);
        *(uint2*)(dl + (size_t)nr * DIM + kq) = make_uint2(l0, l1);
    }
}

// ---------------- router (unchanged, proven) --------------------------------
__global__ void __launch_bounds__(256) router_kernel(
    const float* __restrict__ x,   const float* __restrict__ eps,
    const float* __restrict__ Wr,  const float* __restrict__ br,
    const float* __restrict__ Wn,  const float* __restrict__ bn)
{
    __shared__ float sWr[NEXP][DIM];
    __shared__ float sWn[NEXP][DIM];
    const int tid = threadIdx.x;
    for (int i = tid; i < DIM * NEXP; i += blockDim.x) {
        int d = i >> 3, e = i & 7;
        sWr[e][d] = Wr[i];
        sWn[e][d] = Wn[i];
    }
    __syncthreads();

    const int warp = tid >> 5, lane = tid & 31;
    const int t = blockIdx.x * 8 + warp;

    const float* xr = x + (size_t)t * DIM;
    float xf[16];
#pragma unroll
    for (int i = 0; i < 16; i++) xf[i] = xr[lane + 32 * i];

    float noisy[NEXP];
#pragma unroll
    for (int e = 0; e < NEXP; e++) {
        float ar = 0.f, an = 0.f;
#pragma unroll
        for (int i = 0; i < 16; i++) {
            int d = lane + 32 * i;
            ar = fmaf(xf[i], sWr[e][d], ar);
            an = fmaf(xf[i], sWn[e][d], an);
        }
#pragma unroll
        for (int o = 16; o; o >>= 1) {
            ar += __shfl_xor_sync(0xffffffffu, ar, o);
            an += __shfl_xor_sync(0xffffffffu, an, o);
        }
        float lg = ar + br[e];
        float nl = an + bn[e];
        float sp = fmaxf(nl, 0.f) + log1pf(expf(-fabsf(nl)));
        noisy[e] = lg + eps[(size_t)t * NEXP + e] * sp;
    }

    if (lane == 0) {
        int i1 = 0; float v1 = noisy[0];
#pragma unroll
        for (int e = 1; e < NEXP; e++) if (noisy[e] > v1) { v1 = noisy[e]; i1 = e; }
        int i2 = -1; float v2 = -INFINITY;
#pragma unroll
        for (int e = 0; e < NEXP; e++) if (e != i1 && noisy[e] > v2) { v2 = noisy[e]; i2 = e; }
        float ex = expf(v2 - v1);
        float inv = 1.f / (1.f + ex);
        float g1 = inv, g2 = ex * inv;

        int p1 = atomicAdd(&g_count[i1], 1);
        g_tok[i1][p1] = t; g_gate[i1][p1] = g1; g_slot[i1][p1] = 0;
        int p2 = atomicAdd(&g_count[i2], 1);
        g_tok[i2][p2] = t; g_gate[i2][p2] = g2; g_slot[i2][p2] = 1;
    }
}

// ---------------- grouped expert GEMM via mma.sync (HMMA) -------------------
// Tile 128x128, BK=32, 8 warps in 4(m) x 2(n): warp = 32 rows x 64 cols.
// acc += Ahi*Bhi + Ahi*Blo + Alo*Bhi  (bf16 hi/lo split, fp32 accum)
#define ROW_B   80                       // bytes per smem row (32 bf16 + 16B pad)
#define MAT_B   (128 * ROW_B)            // 10240 bytes per matrix per stage
#define GEMM_SMEM (2 * 4 * MAT_B)        // 81920

__global__ void __launch_bounds__(256, 1) expert_gemm_mma(const float* __restrict__ bk)
{
    const int e   = blockIdx.x / TM_TILES;
    const int mt  = blockIdx.x % TM_TILES;
    const int cnt = g_count[e];
    const int m0  = mt * BM;
    if (m0 >= cnt) return;
    const int nb = blockIdx.y * BN;

    extern __shared__ char smem[];
    __shared__ int   sTok[BM];
    __shared__ float sGate[BM];
    __shared__ int   sSlot[BM];

    const int tid = threadIdx.x, wid = tid >> 5, lane = tid & 31;
    const int warp_m = wid & 3, warp_n = wid >> 2;

    if (tid < BM) {
        int m = m0 + tid;
        bool v = (m < cnt);
        sTok[tid]  = v ? g_tok[e][m] : g_tok[e][m0];
        sGate[tid] = v ? g_gate[e][m] : 0.f;
        sSlot[tid] = v ? (int)g_slot[e][m] : 0;
    }
    __syncthreads();

    const uint32_t sb = smem_u32(smem);

    // --- staging: 2 units of 16B per thread per matrix per stage
    int rowU[2], segU[2];
    uint32_t stOff[2];
    const __nv_bfloat16 *gAh[2], *gAl[2], *gBh[2], *gBl[2];
#pragma unroll
    for (int j = 0; j < 2; j++) {
        int unit = tid + 256 * j;           // 0..511
        rowU[j] = unit >> 2;
        segU[j] = unit & 3;
        stOff[j] = (uint32_t)(rowU[j] * ROW_B + segU[j] * 16);
        int tok = sTok[rowU[j]];
        gAh[j] = g_x_hi + (size_t)tok * DIM + segU[j] * 8;
        gAl[j] = g_x_lo + (size_t)tok * DIM + segU[j] * 8;
        int n = nb + rowU[j];
        gBh[j] = g_wk_hi + ((size_t)e * DIM + n) * DIM + segU[j] * 8;
        gBl[j] = g_wk_lo + ((size_t)e * DIM + n) * DIM + segU[j] * 8;
    }

    // ldmatrix lane offsets
    const uint32_t aLd = (uint32_t)((warp_m * 32 + (lane & 15)) * ROW_B + (lane >> 4) * 16);
    const uint32_t bLd = (uint32_t)((warp_n * 64 + ((lane >> 4) * 8) + (lane & 7)) * ROW_B
                                    + ((lane >> 3) & 1) * 16);

    float acc[2][8][4];
#pragma unroll
    for (int i = 0; i < 2; i++)
#pragma unroll
        for (int t = 0; t < 8; t++)
#pragma unroll
            for (int q = 0; q < 4; q++) acc[i][t][q] = 0.f;

    auto load_stage = [&](int st) {
        const int k0 = st * BK;
        const int buf = st & 1;
        const uint32_t base = sb + buf * (4 * MAT_B);
#pragma unroll
        for (int j = 0; j < 2; j++) {
            cp16(base + 0 * MAT_B + stOff[j], gAh[j] + k0);
            cp16(base + 1 * MAT_B + stOff[j], gAl[j] + k0);
            cp16(base + 2 * MAT_B + stOff[j], gBh[j] + k0);
            cp16(base + 3 * MAT_B + stOff[j], gBl[j] + k0);
        }
        cp_commit();
    };

    load_stage(0);

#pragma unroll 1
    for (int st = 0; st < DIM / BK; st++) {
        if (st + 1 < DIM / BK) { load_stage(st + 1); cp_wait<1>(); }
        else                   { cp_wait<0>(); }
        __syncthreads();

        const uint32_t base = sb + (st & 1) * (4 * MAT_B);
        const uint32_t aHiB = base + 0 * MAT_B + aLd;
        const uint32_t aLoB = base + 1 * MAT_B + aLd;
        const uint32_t bHiB = base + 2 * MAT_B + bLd;
        const uint32_t bLoB = base + 3 * MAT_B + bLd;

#pragma unroll
        for (int kk = 0; kk < 2; kk++) {
            const uint32_t ko = kk * 32;     // 16 bf16 = 32 bytes
            uint32_t aHi[2][4], aLo[2][4], bHi[4][4], bLo[4][4];
#pragma unroll
            for (int i = 0; i < 2; i++) {
                ldsm4(aHi[i][0], aHi[i][1], aHi[i][2], aHi[i][3], aHiB + i * 16 * ROW_B + ko);
                ldsm4(aLo[i][0], aLo[i][1], aLo[i][2], aLo[i][3], aLoB + i * 16 * ROW_B + ko);
            }
#pragma unroll
            for (int p = 0; p < 4; p++) {
                ldsm4(bHi[p][0], bHi[p][1], bHi[p][2], bHi[p][3], bHiB + p * 16 * ROW_B + ko);
                ldsm4(bLo[p][0], bLo[p][1], bLo[p][2], bLo[p][3], bLoB + p * 16 * ROW_B + ko);
            }
#pragma unroll
            for (int i = 0; i < 2; i++)
#pragma unroll
                for (int p = 0; p < 4; p++)
#pragma unroll
                    for (int h = 0; h < 2; h++) {
                        const int t = 2 * p + h;
                        mma16816(acc[i][t], aHi[i], &bHi[p][h * 2]);
                        mma16816(acc[i][t], aHi[i], &bLo[p][h * 2]);
                        mma16816(acc[i][t], aLo[i], &bHi[p][h * 2]);
                    }
        }
        __syncthreads();
    }

    // ---------------- epilogue: gate*(acc+bk) -> slot partial buffer --------
    float2 bkf[8];
    {
        const float* bkp = bk + (size_t)e * DIM + nb + warp_n * 64 + (lane & 3) * 2;
#pragma unroll
        for (int t = 0; t < 8; t++) bkf[t] = *(const float2*)(bkp + t * 8);
    }
#pragma unroll
    for (int i = 0; i < 2; i++) {
#pragma unroll
        for (int half = 0; half < 2; half++) {
            const int mrow = warp_m * 32 + i * 16 + half * 8 + (lane >> 2);
            const int m = m0 + mrow;
            if (m < cnt) {
                const int   tok  = sTok[mrow];
                const float g    = sGate[mrow];
                const int   slot = sSlot[mrow];
                float* op = &g_partial[slot][tok][nb + warp_n * 64 + (lane & 3) * 2];
#pragma unroll
                for (int t = 0; t < 8; t++) {
                    float2 r;
                    r.x = g * (acc[i][t][half * 2 + 0] + bkf[t].x);
                    r.y = g * (acc[i][t][half * 2 + 1] + bkf[t].y);
                    *(float2*)(op + t * 8) = r;
                }
            }
        }
    }
}

// ---------------- combine ----------------------------------------------------
__global__ void combine_kernel(float* __restrict__ out) {
    const size_t i = (size_t)blockIdx.x * blockDim.x + threadIdx.x;
    const float4* p0 = (const float4*)&g_partial[0][0][0];
    const float4* p1 = (const float4*)&g_partial[1][0][0];
    float4 a = p0[i], b = p1[i];
    float4 r;
    r.x = a.x + b.x; r.y = a.y + b.y; r.z = a.z + b.z; r.w = a.w + b.w;
    ((float4*)out)[i] = r;
}

// ---------------- launch -----------------------------------------------------
extern "C" void kernel_launch(void* const* d_in, const int* in_sizes, int n_in,
                              void* d_out, int out_size) {
    const float* x   = (const float*)d_in[0];
    const float* eps = (const float*)d_in[1];
    const float* Wr  = (const float*)d_in[2];
    const float* br  = (const float*)d_in[3];
    const float* Wn  = (const float*)d_in[4];
    const float* bn  = (const float*)d_in[5];
    const float* Wk  = (const float*)d_in[6];
    const float* bk  = (const float*)d_in[7];
    float* out = (float*)d_out;

    cudaFuncSetAttribute(expert_gemm_mma,
                         cudaFuncAttributeMaxDynamicSharedMemorySize, GEMM_SMEM);

    init_counts_kernel<<<1, 32>>>();
    convert_x_kernel<<<(NTOK * DIM / 4) / 256, 256>>>(x);
    convert_wk_kernel<<<dim3(8, 8, 8), 256>>>(Wk);
    router_kernel<<<NTOK / 8, 256>>>(x, eps, Wr, br, Wn, bn);
    dim3 ggrid(NEXP * TM_TILES, DIM / BN);
    expert_gemm_mma<<<ggrid, 256, GEMM_SMEM>>>(bk);
    combine_kernel<<<(NTOK * DIM / 4) / 256, 256>>>(out);
}

// round 4
// speedup vs baseline: 1.5208x; 1.1563x over previous
#include <cuda_runtime.h>
#include <cuda_bf16.h>
#include <math.h>
#include <stdint.h>

#define NTOK  16384
#define DIM   512
#define NEXP  8
#define BM    128
#define BN    128
#define BK    64
#define KSTAGES (DIM / BK)          // 8
#define TM_TILES (NTOK / BM)

// ---------------- static device scratch ------------------------------------
__device__ int            g_count[NEXP];
__device__ int            g_tok [NEXP][NTOK];
__device__ float          g_gate[NEXP][NTOK];
__device__ __nv_bfloat16  g_x_hi[NTOK * DIM];
__device__ __nv_bfloat16  g_x_lo[NTOK * DIM];
__device__ __nv_bfloat16  g_wk_hi[NEXP * DIM * DIM];           // [e][n][k]
__device__ __nv_bfloat16  g_wk_lo[NEXP * DIM * DIM];

// ---------------- helpers ---------------------------------------------------
__device__ __forceinline__ uint32_t smem_u32(const void* p) {
    uint32_t a;
    asm("{ .reg .u64 t; cvta.to.shared.u64 t, %1; cvt.u32.u64 %0, t; }" : "=r"(a) : "l"(p));
    return a;
}
__device__ __forceinline__ void cp16(uint32_t saddr, const void* g) {
    asm volatile("cp.async.cg.shared.global [%0], [%1], 16;" :: "r"(saddr), "l"(g));
}
__device__ __forceinline__ void cp_commit() { asm volatile("cp.async.commit_group;"); }
template<int N> __device__ __forceinline__ void cp_wait() {
    asm volatile("cp.async.wait_group %0;" :: "n"(N));
}
__device__ __forceinline__ void ldsm4(uint32_t& r0, uint32_t& r1, uint32_t& r2, uint32_t& r3,
                                      uint32_t addr) {
    asm volatile("ldmatrix.sync.aligned.m8n8.x4.shared.b16 {%0,%1,%2,%3}, [%4];"
                 : "=r"(r0), "=r"(r1), "=r"(r2), "=r"(r3) : "r"(addr));
}
__device__ __forceinline__ void mma16816(float* c, const uint32_t* a, const uint32_t* b) {
    asm volatile(
        "mma.sync.aligned.m16n8k16.row.col.f32.bf16.bf16.f32 "
        "{%0,%1,%2,%3}, {%4,%5,%6,%7}, {%8,%9}, {%0,%1,%2,%3};"
        : "+f"(c[0]), "+f"(c[1]), "+f"(c[2]), "+f"(c[3])
        : "r"(a[0]), "r"(a[1]), "r"(a[2]), "r"(a[3]), "r"(b[0]), "r"(b[1]));
}
__device__ __forceinline__ void redf(float* p, float v) {
    asm volatile("red.global.add.f32 [%0], %1;" :: "l"(p), "f"(v) : "memory");
}

// ---------------- kernel 0: zero counters + output -------------------------
__global__ void init_counts_kernel() {
    if (threadIdx.x < NEXP) g_count[threadIdx.x] = 0;
}
__global__ void zero_out_kernel(float* __restrict__ out) {
    const size_t i = (size_t)blockIdx.x * blockDim.x + threadIdx.x;
    ((float4*)out)[i] = make_float4(0.f, 0.f, 0.f, 0.f);
}

// ---------------- bf16 hi/lo split ------------------------------------------
__device__ __forceinline__ void cvt2(float a, float b, uint32_t& hi, uint32_t& lo) {
    __nv_bfloat16 ah = __float2bfloat16(a);
    __nv_bfloat16 bh = __float2bfloat16(b);
    __nv_bfloat16 al = __float2bfloat16(a - __bfloat162float(ah));
    __nv_bfloat16 bl = __float2bfloat16(b - __bfloat162float(bh));
    hi = ((uint32_t)__bfloat16_as_ushort(bh) << 16) | (uint32_t)__bfloat16_as_ushort(ah);
    lo = ((uint32_t)__bfloat16_as_ushort(bl) << 16) | (uint32_t)__bfloat16_as_ushort(al);
}

__global__ void convert_x_kernel(const float* __restrict__ x) {
    const size_t i = (size_t)blockIdx.x * blockDim.x + threadIdx.x;
    float4 v = ((const float4*)x)[i];
    uint32_t h0, l0, h1, l1;
    cvt2(v.x, v.y, h0, l0);
    cvt2(v.z, v.w, h1, l1);
    ((uint2*)g_x_hi)[i] = make_uint2(h0, h1);
    ((uint2*)g_x_lo)[i] = make_uint2(l0, l1);
}

__global__ void convert_wk_kernel(const float* __restrict__ Wk) {
    __shared__ float s[64][65];
    const int e = blockIdx.z, kt = blockIdx.y * 64, nt = blockIdx.x * 64;
    const int tid = threadIdx.x;
    const float* src = Wk + ((size_t)e * DIM + kt) * DIM + nt;
#pragma unroll
    for (int j = 0; j < 4; j++) {
        int unit = tid + 256 * j;
        int kr = unit >> 4, nc = (unit & 15) * 4;
        float4 v = *(const float4*)(src + (size_t)kr * DIM + nc);
        s[kr][nc + 0] = v.x; s[kr][nc + 1] = v.y;
        s[kr][nc + 2] = v.z; s[kr][nc + 3] = v.w;
    }
    __syncthreads();
    __nv_bfloat16* dh = g_wk_hi + ((size_t)e * DIM + nt) * DIM + kt;
    __nv_bfloat16* dl = g_wk_lo + ((size_t)e * DIM + nt) * DIM + kt;
#pragma unroll
    for (int j = 0; j < 4; j++) {
        int unit = tid + 256 * j;
        int nr = unit >> 4, kq = (unit & 15) * 4;
        float a = s[kq + 0][nr], b = s[kq + 1][nr];
        float c = s[kq + 2][nr], d = s[kq + 3][nr];
        uint32_t h0, l0, h1, l1;
        cvt2(a, b, h0, l0);
        cvt2(c, d, h1, l1);
        *(uint2*)(dh + (size_t)nr * DIM + kq) = make_uint2(h0, h1);
        *(uint2*)(dl + (size_t)nr * DIM + kq) = make_uint2(l0, l1);
    }
}

// ---------------- router: 4 tokens per warp, float4 broadcast weights -------
// block = 256 thr = 8 warps = 32 tokens; grid = NTOK/32 = 512
__global__ void __launch_bounds__(256) router_kernel(
    const float* __restrict__ x,   const float* __restrict__ eps,
    const float* __restrict__ Wr,  const float* __restrict__ br,
    const float* __restrict__ Wn,  const float* __restrict__ bn)
{
    __shared__ float4 sWr4[NEXP][DIM / 4];
    __shared__ float4 sWn4[NEXP][DIM / 4];
    const int tid = threadIdx.x;
    {
        float* pr = (float*)sWr4;
        float* pn = (float*)sWn4;
        for (int i = tid; i < DIM * NEXP; i += 256) {
            int d = i >> 3, e = i & 7;
            pr[e * DIM + d] = Wr[i];
            pn[e * DIM + d] = Wn[i];
        }
    }
    __syncthreads();

    const int warp = tid >> 5, lane = tid & 31;
    const int grp = lane >> 3, sl = lane & 7;      // 4 token-groups of 8 lanes
    const int t = blockIdx.x * 32 + warp * 4 + grp;

    const float4* xr = (const float4*)(x + (size_t)t * DIM);
    float4 xf[16];
#pragma unroll
    for (int i = 0; i < 16; i++) xf[i] = xr[sl + 8 * i];

    float noisy[NEXP];
#pragma unroll
    for (int e = 0; e < NEXP; e++) {
        float ar = 0.f, an = 0.f;
#pragma unroll
        for (int i = 0; i < 16; i++) {
            float4 wr = sWr4[e][sl + 8 * i];
            float4 wn = sWn4[e][sl + 8 * i];
            ar = fmaf(xf[i].x, wr.x, ar); ar = fmaf(xf[i].y, wr.y, ar);
            ar = fmaf(xf[i].z, wr.z, ar); ar = fmaf(xf[i].w, wr.w, ar);
            an = fmaf(xf[i].x, wn.x, an); an = fmaf(xf[i].y, wn.y, an);
            an = fmaf(xf[i].z, wn.z, an); an = fmaf(xf[i].w, wn.w, an);
        }
#pragma unroll
        for (int o = 4; o; o >>= 1) {
            ar += __shfl_xor_sync(0xffffffffu, ar, o);
            an += __shfl_xor_sync(0xffffffffu, an, o);
        }
        float lg = ar + br[e];
        float nl = an + bn[e];
        float sp = fmaxf(nl, 0.f) + log1pf(expf(-fabsf(nl)));
        noisy[e] = lg + eps[(size_t)t * NEXP + e] * sp;
    }

    if (sl == 0) {
        int i1 = 0; float v1 = noisy[0];
#pragma unroll
        for (int e = 1; e < NEXP; e++) if (noisy[e] > v1) { v1 = noisy[e]; i1 = e; }
        int i2 = -1; float v2 = -INFINITY;
#pragma unroll
        for (int e = 0; e < NEXP; e++) if (e != i1 && noisy[e] > v2) { v2 = noisy[e]; i2 = e; }
        float ex = expf(v2 - v1);
        float inv = 1.f / (1.f + ex);
        float g1 = inv, g2 = ex * inv;

        int p1 = atomicAdd(&g_count[i1], 1);
        g_tok[i1][p1] = t; g_gate[i1][p1] = g1;
        int p2 = atomicAdd(&g_count[i2], 1);
        g_tok[i2][p2] = t; g_gate[i2][p2] = g2;
    }
}

// ---------------- grouped expert GEMM: HMMA, BK=64, 3-stage ring ------------
#define ROW_B   144                      // 64 bf16 (128B) + 16B pad
#define MAT_B   (128 * ROW_B)            // 18432 bytes per matrix per stage
#define STAGE_B (4 * MAT_B)              // 73728
#define GEMM_SMEM (3 * STAGE_B)          // 221184

__global__ void __launch_bounds__(256, 1) expert_gemm_mma(
    const float* __restrict__ bk, float* __restrict__ out)
{
    const int e   = blockIdx.x / TM_TILES;
    const int mt  = blockIdx.x % TM_TILES;
    const int cnt = g_count[e];
    const int m0  = mt * BM;
    if (m0 >= cnt) return;
    const int nb = blockIdx.y * BN;

    extern __shared__ char smem[];
    __shared__ int   sTok[BM];
    __shared__ float sGate[BM];

    const int tid = threadIdx.x, wid = tid >> 5, lane = tid & 31;
    const int warp_m = wid & 3, warp_n = wid >> 2;

    if (tid < BM) {
        int m = m0 + tid;
        bool v = (m < cnt);
        sTok[tid]  = v ? g_tok[e][m] : g_tok[e][m0];
        sGate[tid] = v ? g_gate[e][m] : 0.f;
    }
    __syncthreads();

    const uint32_t sb = smem_u32(smem);

    // staging: 4 units of 16B per thread per matrix per stage (1024 units/mat)
    uint32_t stOff[4];
    size_t   aOff[4], bOff[4];
#pragma unroll
    for (int j = 0; j < 4; j++) {
        int unit = tid + 256 * j;             // 0..1023
        int row = unit >> 3, seg = unit & 7;
        stOff[j] = (uint32_t)(row * ROW_B + seg * 16);
        aOff[j] = (size_t)sTok[row] * DIM + seg * 8;
        bOff[j] = ((size_t)e * DIM + nb + row) * DIM + seg * 8;
    }

    const uint32_t aLd = (uint32_t)((warp_m * 32 + (lane & 15)) * ROW_B + (lane >> 4) * 16);
    const uint32_t bLd = (uint32_t)((warp_n * 64 + ((lane >> 4) * 8) + (lane & 7)) * ROW_B
                                    + ((lane >> 3) & 1) * 16);

    float acc[2][8][4];
#pragma unroll
    for (int i = 0; i < 2; i++)
#pragma unroll
        for (int t = 0; t < 8; t++)
#pragma unroll
            for (int q = 0; q < 4; q++) acc[i][t][q] = 0.f;

    auto load_stage = [&](int st) {
        const int k0 = st * BK;
        const uint32_t base = sb + (st % 3) * STAGE_B;
#pragma unroll
        for (int j = 0; j < 4; j++) {
            cp16(base + 0 * MAT_B + stOff[j], g_x_hi  + aOff[j] + k0);
            cp16(base + 1 * MAT_B + stOff[j], g_x_lo  + aOff[j] + k0);
            cp16(base + 2 * MAT_B + stOff[j], g_wk_hi + bOff[j] + k0);
            cp16(base + 3 * MAT_B + stOff[j], g_wk_lo + bOff[j] + k0);
        }
        cp_commit();
    };

    load_stage(0);
    load_stage(1);

#pragma unroll 1
    for (int st = 0; st < KSTAGES; st++) {
        if (st + 1 < KSTAGES) cp_wait<1>();
        else                  cp_wait<0>();
        __syncthreads();
        if (st + 2 < KSTAGES) load_stage(st + 2);   // overlaps compute below

        const uint32_t base = sb + (st % 3) * STAGE_B;
        const uint32_t aHiB = base + 0 * MAT_B + aLd;
        const uint32_t aLoB = base + 1 * MAT_B + aLd;
        const uint32_t bHiB = base + 2 * MAT_B + bLd;
        const uint32_t bLoB = base + 3 * MAT_B + bLd;

#pragma unroll
        for (int kk = 0; kk < 4; kk++) {
            const uint32_t ko = kk * 32;            // 16 bf16 per k-slice
            uint32_t aHi[2][4], aLo[2][4], bHi[4][4], bLo[4][4];
#pragma unroll
            for (int i = 0; i < 2; i++) {
                ldsm4(aHi[i][0], aHi[i][1], aHi[i][2], aHi[i][3], aHiB + i * 16 * ROW_B + ko);
                ldsm4(aLo[i][0], aLo[i][1], aLo[i][2], aLo[i][3], aLoB + i * 16 * ROW_B + ko);
            }
#pragma unroll
            for (int p = 0; p < 4; p++) {
                ldsm4(bHi[p][0], bHi[p][1], bHi[p][2], bHi[p][3], bHiB + p * 16 * ROW_B + ko);
                ldsm4(bLo[p][0], bLo[p][1], bLo[p][2], bLo[p][3], bLoB + p * 16 * ROW_B + ko);
            }
#pragma unroll
            for (int i = 0; i < 2; i++)
#pragma unroll
                for (int p = 0; p < 4; p++)
#pragma unroll
                    for (int h = 0; h < 2; h++) {
                        const int t = 2 * p + h;
                        mma16816(acc[i][t], aHi[i], &bHi[p][h * 2]);
                        mma16816(acc[i][t], aHi[i], &bLo[p][h * 2]);
                        mma16816(acc[i][t], aLo[i], &bHi[p][h * 2]);
                    }
        }
    }

    // ---------------- epilogue: red.global.add of gate*(acc+bk) -------------
    float2 bkf[8];
    {
        const float* bkp = bk + (size_t)e * DIM + nb + warp_n * 64 + (lane & 3) * 2;
#pragma unroll
        for (int t = 0; t < 8; t++) bkf[t] = *(const float2*)(bkp + t * 8);
    }
#pragma unroll
    for (int i = 0; i < 2; i++) {
#pragma unroll
        for (int half = 0; half < 2; half++) {
            const int mrow = warp_m * 32 + i * 16 + half * 8 + (lane >> 2);
            const int m = m0 + mrow;
            if (m < cnt) {
                const int   tok = sTok[mrow];
                const float g   = sGate[mrow];
                float* op = out + (size_t)tok * DIM + nb + warp_n * 64 + (lane & 3) * 2;
#pragma unroll
                for (int t = 0; t < 8; t++) {
                    redf(op + t * 8 + 0, g * (acc[i][t][half * 2 + 0] + bkf[t].x));
                    redf(op + t * 8 + 1, g * (acc[i][t][half * 2 + 1] + bkf[t].y));
                }
            }
        }
    }
}

// ---------------- launch -----------------------------------------------------
extern "C" void kernel_launch(void* const* d_in, const int* in_sizes, int n_in,
                              void* d_out, int out_size) {
    const float* x   = (const float*)d_in[0];
    const float* eps = (const float*)d_in[1];
    const float* Wr  = (const float*)d_in[2];
    const float* br  = (const float*)d_in[3];
    const float* Wn  = (const float*)d_in[4];
    const float* bn  = (const float*)d_in[5];
    const float* Wk  = (const float*)d_in[6];
    const float* bk  = (const float*)d_in[7];
    float* out = (float*)d_out;

    cudaFuncSetAttribute(expert_gemm_mma,
                         cudaFuncAttributeMaxDynamicSharedMemorySize, GEMM_SMEM);

    init_counts_kernel<<<1, 32>>>();
    zero_out_kernel<<<(NTOK * DIM / 4) / 256, 256>>>(out);
    convert_x_kernel<<<(NTOK * DIM / 4) / 256, 256>>>(x);
    convert_wk_kernel<<<dim3(8, 8, 8), 256>>>(Wk);
    router_kernel<<<NTOK / 32, 256>>>(x, eps, Wr, br, Wn, bn);
    dim3 ggrid(NEXP * TM_TILES, DIM / BN);
    expert_gemm_mma<<<ggrid, 256, GEMM_SMEM>>>(bk, out);
}

// round 5
// speedup vs baseline: 1.8447x; 1.2130x over previous
#include <cuda_runtime.h>
#include <cuda_fp16.h>
#include <math.h>
#include <stdint.h>

#define NTOK  16384
#define DIM   512
#define NEXP  8
#define BM    128
#define BN    128
#define BK    64
#define KSTAGES (DIM / BK)          // 8
#define TM_TILES (NTOK / BM)

// ---------------- static device scratch ------------------------------------
__device__ int     g_count[NEXP];
__device__ int     g_tok [NEXP][NTOK];
__device__ float   g_gate[NEXP][NTOK];
__device__ __half  g_x_hi[NTOK * DIM];
__device__ __half  g_x_lo[NTOK * DIM];
__device__ __half  g_wk  [NEXP * DIM * DIM];        // [e][n][k] fp16
// ---------------- helpers ---------------------------------------------------
__device__ __forceinline__ uint32_t smem_u32(const void* p) {
    uint32_t a;
    asm("{ .reg .u64 t; cvta.to.shared.u64 t, %1; cvt.u32.u64 %0, t; }" : "=r"(a) : "l"(p));
    return a;
}
__device__ __forceinline__ void cp16(uint32_t saddr, const void* g) {
    asm volatile("cp.async.cg.shared.global [%0], [%1], 16;" :: "r"(saddr), "l"(g));
}
__device__ __forceinline__ void cp_commit() { asm volatile("cp.async.commit_group;"); }
template<int N> __device__ __forceinline__ void cp_wait() {
    asm volatile("cp.async.wait_group %0;" :: "n"(N));
}
__device__ __forceinline__ void ldsm4(uint32_t& r0, uint32_t& r1, uint32_t& r2, uint32_t& r3,
                                      uint32_t addr) {
    asm volatile("ldmatrix.sync.aligned.m8n8.x4.shared.b16 {%0,%1,%2,%3}, [%4];"
                 : "=r"(r0), "=r"(r1), "=r"(r2), "=r"(r3) : "r"(addr));
}
__device__ __forceinline__ void mma16816(float* c, const uint32_t* a, const uint32_t* b) {
    asm volatile(
        "mma.sync.aligned.m16n8k16.row.col.f32.f16.f16.f32 "
        "{%0,%1,%2,%3}, {%4,%5,%6,%7}, {%8,%9}, {%0,%1,%2,%3};"
        : "+f"(c[0]), "+f"(c[1]), "+f"(c[2]), "+f"(c[3])
        : "r"(a[0]), "r"(a[1]), "r"(a[2]), "r"(a[3]), "r"(b[0]), "r"(b[1]));
}
__device__ __forceinline__ void redf(float* p, float v) {
    asm volatile("red.global.add.f32 [%0], %1;" :: "l"(p), "f"(v) : "memory");
}

// ---------------- kernel 0: zero counters + output --------------------------
__global__ void init_counts_kernel() {
    if (threadIdx.x < NEXP) g_count[threadIdx.x] = 0;
}
__global__ void zero_out_kernel(float* __restrict__ out) {
    const size_t i = (size_t)blockIdx.x * blockDim.x + threadIdx.x;
    ((float4*)out)[i] = make_float4(0.f, 0.f, 0.f, 0.f);
}

// ---------------- fp16 hi/lo split for x ------------------------------------
__device__ __forceinline__ void cvt2h(float a, float b, uint32_t& hi, uint32_t& lo) {
    __half ah = __float2half_rn(a);
    __half bh = __float2half_rn(b);
    __half al = __float2half_rn(a - __half2float(ah));
    __half bl = __float2half_rn(b - __half2float(bh));
    hi = ((uint32_t)__half_as_ushort(bh) << 16) | (uint32_t)__half_as_ushort(ah);
    lo = ((uint32_t)__half_as_ushort(bl) << 16) | (uint32_t)__half_as_ushort(al);
}

__global__ void convert_x_kernel(const float* __restrict__ x) {
    const size_t i = (size_t)blockIdx.x * blockDim.x + threadIdx.x;
    float4 v = ((const float4*)x)[i];
    uint32_t h0, l0, h1, l1;
    cvt2h(v.x, v.y, h0, l0);
    cvt2h(v.z, v.w, h1, l1);
    ((uint2*)g_x_hi)[i] = make_uint2(h0, h1);
    ((uint2*)g_x_lo)[i] = make_uint2(l0, l1);
}

// Wk [e][k][n] fp32 -> [e][n][k] fp16 (transpose via smem)
__global__ void convert_wk_kernel(const float* __restrict__ Wk) {
    __shared__ float s[64][65];
    const int e = blockIdx.z, kt = blockIdx.y * 64, nt = blockIdx.x * 64;
    const int tid = threadIdx.x;
    const float* src = Wk + ((size_t)e * DIM + kt) * DIM + nt;
#pragma unroll
    for (int j = 0; j < 4; j++) {
        int unit = tid + 256 * j;
        int kr = unit >> 4, nc = (unit & 15) * 4;
        float4 v = *(const float4*)(src + (size_t)kr * DIM + nc);
        s[kr][nc + 0] = v.x; s[kr][nc + 1] = v.y;
        s[kr][nc + 2] = v.z; s[kr][nc + 3] = v.w;
    }
    __syncthreads();
    __half* dh = g_wk + ((size_t)e * DIM + nt) * DIM + kt;
#pragma unroll
    for (int j = 0; j < 4; j++) {
        int unit = tid + 256 * j;
        int nr = unit >> 4, kq = (unit & 15) * 4;
        __half2 p0 = __floats2half2_rn(s[kq + 0][nr], s[kq + 1][nr]);
        __half2 p1 = __floats2half2_rn(s[kq + 2][nr], s[kq + 3][nr]);
        *(uint2*)(dh + (size_t)nr * DIM + kq) =
            make_uint2(*(uint32_t*)&p0, *(uint32_t*)&p1);
    }
}

// ---------------- router: 4 tokens per warp (proven at ~10us) ----------------
__global__ void __launch_bounds__(256) router_kernel(
    const float* __restrict__ x,   const float* __restrict__ eps,
    const float* __restrict__ Wr,  const float* __restrict__ br,
    const float* __restrict__ Wn,  const float* __restrict__ bn)
{
    __shared__ float4 sWr4[NEXP][DIM / 4];
    __shared__ float4 sWn4[NEXP][DIM / 4];
    const int tid = threadIdx.x;
    {
        float* pr = (float*)sWr4;
        float* pn = (float*)sWn4;
        for (int i = tid; i < DIM * NEXP; i += 256) {
            int d = i >> 3, e = i & 7;
            pr[e * DIM + d] = Wr[i];
            pn[e * DIM + d] = Wn[i];
        }
    }
    __syncthreads();

    const int warp = tid >> 5, lane = tid & 31;
    const int grp = lane >> 3, sl = lane & 7;
    const int t = blockIdx.x * 32 + warp * 4 + grp;

    const float4* xr = (const float4*)(x + (size_t)t * DIM);
    float4 xf[16];
#pragma unroll
    for (int i = 0; i < 16; i++) xf[i] = xr[sl + 8 * i];

    float noisy[NEXP];
#pragma unroll
    for (int e = 0; e < NEXP; e++) {
        float ar = 0.f, an = 0.f;
#pragma unroll
        for (int i = 0; i < 16; i++) {
            float4 wr = sWr4[e][sl + 8 * i];
            float4 wn = sWn4[e][sl + 8 * i];
            ar = fmaf(xf[i].x, wr.x, ar); ar = fmaf(xf[i].y, wr.y, ar);
            ar = fmaf(xf[i].z, wr.z, ar); ar = fmaf(xf[i].w, wr.w, ar);
            an = fmaf(xf[i].x, wn.x, an); an = fmaf(xf[i].y, wn.y, an);
            an = fmaf(xf[i].z, wn.z, an); an = fmaf(xf[i].w, wn.w, an);
        }
#pragma unroll
        for (int o = 4; o; o >>= 1) {
            ar += __shfl_xor_sync(0xffffffffu, ar, o);
            an += __shfl_xor_sync(0xffffffffu, an, o);
        }
        float lg = ar + br[e];
        float nl = an + bn[e];
        float sp = fmaxf(nl, 0.f) + log1pf(expf(-fabsf(nl)));
        noisy[e] = lg + eps[(size_t)t * NEXP + e] * sp;
    }

    if (sl == 0) {
        int i1 = 0; float v1 = noisy[0];
#pragma unroll
        for (int e = 1; e < NEXP; e++) if (noisy[e] > v1) { v1 = noisy[e]; i1 = e; }
        int i2 = -1; float v2 = -INFINITY;
#pragma unroll
        for (int e = 0; e < NEXP; e++) if (e != i1 && noisy[e] > v2) { v2 = noisy[e]; i2 = e; }
        float ex = expf(v2 - v1);
        float inv = 1.f / (1.f + ex);
        float g1 = inv, g2 = ex * inv;

        int p1 = atomicAdd(&g_count[i1], 1);
        g_tok[i1][p1] = t; g_gate[i1][p1] = g1;
        int p2 = atomicAdd(&g_count[i2], 1);
        g_tok[i2][p2] = t; g_gate[i2][p2] = g2;
    }
}

// ---------------- grouped expert GEMM: fp16 HMMA, 2 MMA passes ---------------
// acc += Ahi*B + Alo*B   (A split into fp16 hi/lo; B single fp16)
#define ROW_B   144                      // 64 fp16 (128B) + 16B pad
#define MAT_B   (128 * ROW_B)            // 18432 bytes per matrix per stage
#define STAGE_B (3 * MAT_B)              // 55296 (Ahi, Alo, B)
#define GEMM_SMEM (3 * STAGE_B)          // 165888

__global__ void __launch_bounds__(256, 1) expert_gemm_mma(
    const float* __restrict__ bk, float* __restrict__ out)
{
    const int e   = blockIdx.x / TM_TILES;
    const int mt  = blockIdx.x % TM_TILES;
    const int cnt = g_count[e];
    const int m0  = mt * BM;
    if (m0 >= cnt) return;
    const int nb = blockIdx.y * BN;

    extern __shared__ char smem[];
    __shared__ int   sTok[BM];
    __shared__ float sGate[BM];

    const int tid = threadIdx.x, wid = tid >> 5, lane = tid & 31;
    const int warp_m = wid & 3, warp_n = wid >> 2;

    if (tid < BM) {
        int m = m0 + tid;
        bool v = (m < cnt);
        sTok[tid]  = v ? g_tok[e][m] : g_tok[e][m0];
        sGate[tid] = v ? g_gate[e][m] : 0.f;
    }
    __syncthreads();

    const uint32_t sb = smem_u32(smem);

    uint32_t stOff[4];
    size_t   aOff[4], bOff[4];
#pragma unroll
    for (int j = 0; j < 4; j++) {
        int unit = tid + 256 * j;             // 0..1023
        int row = unit >> 3, seg = unit & 7;
        stOff[j] = (uint32_t)(row * ROW_B + seg * 16);
        aOff[j] = (size_t)sTok[row] * DIM + seg * 8;
        bOff[j] = ((size_t)e * DIM + nb + row) * DIM + seg * 8;
    }

    const uint32_t aLd = (uint32_t)((warp_m * 32 + (lane & 15)) * ROW_B + (lane >> 4) * 16);
    const uint32_t bLd = (uint32_t)((warp_n * 64 + ((lane >> 4) * 8) + (lane & 7)) * ROW_B
                                    + ((lane >> 3) & 1) * 16);

    float acc[2][8][4];
#pragma unroll
    for (int i = 0; i < 2; i++)
#pragma unroll
        for (int t = 0; t < 8; t++)
#pragma unroll
            for (int q = 0; q < 4; q++) acc[i][t][q] = 0.f;

    auto load_stage = [&](int st) {
        const int k0 = st * BK;
        const uint32_t base = sb + (st % 3) * STAGE_B;
#pragma unroll
        for (int j = 0; j < 4; j++) {
            cp16(base + 0 * MAT_B + stOff[j], g_x_hi + aOff[j] + k0);
            cp16(base + 1 * MAT_B + stOff[j], g_x_lo + aOff[j] + k0);
            cp16(base + 2 * MAT_B + stOff[j], g_wk   + bOff[j] + k0);
        }
        cp_commit();
    };

    load_stage(0);
    load_stage(1);

#pragma unroll 1
    for (int st = 0; st < KSTAGES; st++) {
        if (st + 1 < KSTAGES) cp_wait<1>();
        else                  cp_wait<0>();
        __syncthreads();
        if (st + 2 < KSTAGES) load_stage(st + 2);

        const uint32_t base = sb + (st % 3) * STAGE_B;
        const uint32_t aHiB = base + 0 * MAT_B + aLd;
        const uint32_t aLoB = base + 1 * MAT_B + aLd;
        const uint32_t bB   = base + 2 * MAT_B + bLd;

#pragma unroll
        for (int kk = 0; kk < 4; kk++) {
            const uint32_t ko = kk * 32;
            uint32_t aHi[2][4], aLo[2][4], bF[4][4];
#pragma unroll
            for (int i = 0; i < 2; i++) {
                ldsm4(aHi[i][0], aHi[i][1], aHi[i][2], aHi[i][3], aHiB + i * 16 * ROW_B + ko);
                ldsm4(aLo[i][0], aLo[i][1], aLo[i][2], aLo[i][3], aLoB + i * 16 * ROW_B + ko);
            }
#pragma unroll
            for (int p = 0; p < 4; p++)
                ldsm4(bF[p][0], bF[p][1], bF[p][2], bF[p][3], bB + p * 16 * ROW_B + ko);
#pragma unroll
            for (int i = 0; i < 2; i++)
#pragma unroll
                for (int p = 0; p < 4; p++)
#pragma unroll
                    for (int h = 0; h < 2; h++) {
                        const int t = 2 * p + h;
                        mma16816(acc[i][t], aHi[i], &bF[p][h * 2]);
                        mma16816(acc[i][t], aLo[i], &bF[p][h * 2]);
                    }
        }
    }

    // ---------------- epilogue: red.global.add of gate*(acc+bk) --------------
    float2 bkf[8];
    {
        const float* bkp = bk + (size_t)e * DIM + nb + warp_n * 64 + (lane & 3) * 2;
#pragma unroll
        for (int t = 0; t < 8; t++) bkf[t] = *(const float2*)(bkp + t * 8);
    }
#pragma unroll
    for (int i = 0; i < 2; i++) {
#pragma unroll
        for (int half = 0; half < 2; half++) {
            const int mrow = warp_m * 32 + i * 16 + half * 8 + (lane >> 2);
            const int m = m0 + mrow;
            if (m < cnt) {
                const int   tok = sTok[mrow];
                const float g   = sGate[mrow];
                float* op = out + (size_t)tok * DIM + nb + warp_n * 64 + (lane & 3) * 2;
#pragma unroll
                for (int t = 0; t < 8; t++) {
                    redf(op + t * 8 + 0, g * (acc[i][t][half * 2 + 0] + bkf[t].x));
                    redf(op + t * 8 + 1, g * (acc[i][t][half * 2 + 1] + bkf[t].y));
                }
            }
        }
    }
}

// ---------------- launch -----------------------------------------------------
extern "C" void kernel_launch(void* const* d_in, const int* in_sizes, int n_in,
                              void* d_out, int out_size) {
    const float* x   = (const float*)d_in[0];
    const float* eps = (const float*)d_in[1];
    const float* Wr  = (const float*)d_in[2];
    const float* br  = (const float*)d_in[3];
    const float* Wn  = (const float*)d_in[4];
    const float* bn  = (const float*)d_in[5];
    const float* Wk  = (const float*)d_in[6];
    const float* bk  = (const float*)d_in[7];
    float* out = (float*)d_out;

    cudaFuncSetAttribute(expert_gemm_mma,
                         cudaFuncAttributeMaxDynamicSharedMemorySize, GEMM_SMEM);

    init_counts_kernel<<<1, 32>>>();
    zero_out_kernel<<<(NTOK * DIM / 4) / 256, 256>>>(out);
    convert_x_kernel<<<(NTOK * DIM / 4) / 256, 256>>>(x);
    convert_wk_kernel<<<dim3(8, 8, 8), 256>>>(Wk);
    router_kernel<<<NTOK / 32, 256>>>(x, eps, Wr, br, Wn, bn);
    dim3 ggrid(NEXP * TM_TILES, DIM / BN);
    expert_gemm_mma<<<ggrid, 256, GEMM_SMEM>>>(bk, out);
}

// round 8
// speedup vs baseline: 2.7473x; 1.4893x over previous
#include <cuda_runtime.h>
#include <cuda_fp16.h>
#include <math.h>
#include <stdint.h>

#define NTOK  16384
#define DIM   512
#define NEXP  8
#define BM    128
#define BN    128
#define BK    64
#define KSTAGES (DIM / BK)          // 8
#define TM_TILES (NTOK / BM)

// ---------------- static device scratch ------------------------------------
__device__ int     g_count[NEXP];
__device__ int     g_tok [NEXP][NTOK];
__device__ float   g_gate[NEXP][NTOK];
__device__ __half  g_x  [NTOK * DIM];               // fp16 x
__device__ __half  g_wk [NEXP * DIM * DIM];         // [e][n][k] fp16

// ---------------- helpers ---------------------------------------------------
__device__ __forceinline__ uint32_t smem_u32(const void* p) {
    uint32_t a;
    asm("{ .reg .u64 t; cvta.to.shared.u64 t, %1; cvt.u32.u64 %0, t; }" : "=r"(a) : "l"(p));
    return a;
}
__device__ __forceinline__ void cp16(uint32_t saddr, const void* g) {
    asm volatile("cp.async.cg.shared.global [%0], [%1], 16;" :: "r"(saddr), "l"(g));
}
__device__ __forceinline__ void cp_commit() { asm volatile("cp.async.commit_group;"); }
template<int N> __device__ __forceinline__ void cp_wait() {
    asm volatile("cp.async.wait_group %0;" :: "n"(N));
}
__device__ __forceinline__ void ldsm4(uint32_t& r0, uint32_t& r1, uint32_t& r2, uint32_t& r3,
                                      uint32_t addr) {
    asm volatile("ldmatrix.sync.aligned.m8n8.x4.shared.b16 {%0,%1,%2,%3}, [%4];"
                 : "=r"(r0), "=r"(r1), "=r"(r2), "=r"(r3) : "r"(addr));
}
__device__ __forceinline__ void mma16816(float* c, const uint32_t* a, const uint32_t* b) {
    asm volatile(
        "mma.sync.aligned.m16n8k16.row.col.f32.f16.f16.f32 "
        "{%0,%1,%2,%3}, {%4,%5,%6,%7}, {%8,%9}, {%0,%1,%2,%3};"
        : "+f"(c[0]), "+f"(c[1]), "+f"(c[2]), "+f"(c[3])
        : "r"(a[0]), "r"(a[1]), "r"(a[2]), "r"(a[3]), "r"(b[0]), "r"(b[1]));
}
__device__ __forceinline__ void redf(float* p, float v) {
    asm volatile("red.global.add.f32 [%0], %1;" :: "l"(p), "f"(v) : "memory");
}

// ---------------- kernel 0: zero counters + output --------------------------
__global__ void init_counts_kernel() {
    if (threadIdx.x < NEXP) g_count[threadIdx.x] = 0;
}
__global__ void zero_out_kernel(float* __restrict__ out) {
    const size_t i = (size_t)blockIdx.x * blockDim.x + threadIdx.x;
    ((float4*)out)[i] = make_float4(0.f, 0.f, 0.f, 0.f);
}

// ---------------- convert x -> fp16 -----------------------------------------
__global__ void convert_x_kernel(const float* __restrict__ x) {
    const size_t i = (size_t)blockIdx.x * blockDim.x + threadIdx.x;
    float4 v = ((const float4*)x)[i];
    __half2 p0 = __floats2half2_rn(v.x, v.y);
    __half2 p1 = __floats2half2_rn(v.z, v.w);
    ((uint2*)g_x)[i] = make_uint2(*(uint32_t*)&p0, *(uint32_t*)&p1);
}

// Wk [e][k][n] fp32 -> [e][n][k] fp16 (transpose via smem)
__global__ void convert_wk_kernel(const float* __restrict__ Wk) {
    __shared__ float s[64][65];
    const int e = blockIdx.z, kt = blockIdx.y * 64, nt = blockIdx.x * 64;
    const int tid = threadIdx.x;
    const float* src = Wk + ((size_t)e * DIM + kt) * DIM + nt;
#pragma unroll
    for (int j = 0; j < 4; j++) {
        int unit = tid + 256 * j;
        int kr = unit >> 4, nc = (unit & 15) * 4;
        float4 v = *(const float4*)(src + (size_t)kr * DIM + nc);
        s[kr][nc + 0] = v.x; s[kr][nc + 1] = v.y;
        s[kr][nc + 2] = v.z; s[kr][nc + 3] = v.w;
    }
    __syncthreads();
    __half* dh = g_wk + ((size_t)e * DIM + nt) * DIM + kt;
#pragma unroll
    for (int j = 0; j < 4; j++) {
        int unit = tid + 256 * j;
        int nr = unit >> 4, kq = (unit & 15) * 4;
        __half2 p0 = __floats2half2_rn(s[kq + 0][nr], s[kq + 1][nr]);
        __half2 p1 = __floats2half2_rn(s[kq + 2][nr], s[kq + 3][nr]);
        *(uint2*)(dh + (size_t)nr * DIM + kq) =
            make_uint2(*(uint32_t*)&p0, *(uint32_t*)&p1);
    }
}

// ---------------- router: 4 tokens per warp (proven) ------------------------
__global__ void __launch_bounds__(256) router_kernel(
    const float* __restrict__ x,   const float* __restrict__ eps,
    const float* __restrict__ Wr,  const float* __restrict__ br,
    const float* __restrict__ Wn,  const float* __restrict__ bn)
{
    __shared__ float4 sWr4[NEXP][DIM / 4];
    __shared__ float4 sWn4[NEXP][DIM / 4];
    const int tid = threadIdx.x;
    {
        float* pr = (float*)sWr4;
        float* pn = (float*)sWn4;
        for (int i = tid; i < DIM * NEXP; i += 256) {
            int d = i >> 3, e = i & 7;
            pr[e * DIM + d] = Wr[i];
            pn[e * DIM + d] = Wn[i];
        }
    }
    __syncthreads();

    const int warp = tid >> 5, lane = tid & 31;
    const int grp = lane >> 3, sl = lane & 7;
    const int t = blockIdx.x * 32 + warp * 4 + grp;

    const float4* xr = (const float4*)(x + (size_t)t * DIM);
    float4 xf[16];
#pragma unroll
    for (int i = 0; i < 16; i++) xf[i] = xr[sl + 8 * i];

    float noisy[NEXP];
#pragma unroll
    for (int e = 0; e < NEXP; e++) {
        float ar = 0.f, an = 0.f;
#pragma unroll
        for (int i = 0; i < 16; i++) {
            float4 wr = sWr4[e][sl + 8 * i];
            float4 wn = sWn4[e][sl + 8 * i];
            ar = fmaf(xf[i].x, wr.x, ar); ar = fmaf(xf[i].y, wr.y, ar);
            ar = fmaf(xf[i].z, wr.z, ar); ar = fmaf(xf[i].w, wr.w, ar);
            an = fmaf(xf[i].x, wn.x, an); an = fmaf(xf[i].y, wn.y, an);
            an = fmaf(xf[i].z, wn.z, an); an = fmaf(xf[i].w, wn.w, an);
        }
#pragma unroll
        for (int o = 4; o; o >>= 1) {
            ar += __shfl_xor_sync(0xffffffffu, ar, o);
            an += __shfl_xor_sync(0xffffffffu, an, o);
        }
        float lg = ar + br[e];
        float nl = an + bn[e];
        float sp = fmaxf(nl, 0.f) + log1pf(expf(-fabsf(nl)));
        noisy[e] = lg + eps[(size_t)t * NEXP + e] * sp;
    }

    if (sl == 0) {
        int i1 = 0; float v1 = noisy[0];
#pragma unroll
        for (int e = 1; e < NEXP; e++) if (noisy[e] > v1) { v1 = noisy[e]; i1 = e; }
        int i2 = -1; float v2 = -INFINITY;
#pragma unroll
        for (int e = 0; e < NEXP; e++) if (e != i1 && noisy[e] > v2) { v2 = noisy[e]; i2 = e; }
        float ex = expf(v2 - v1);
        float inv = 1.f / (1.f + ex);
        float g1 = inv, g2 = ex * inv;

        int p1 = atomicAdd(&g_count[i1], 1);
        g_tok[i1][p1] = t; g_gate[i1][p1] = g1;
        int p2 = atomicAdd(&g_count[i2], 1);
        g_tok[i2][p2] = t; g_gate[i2][p2] = g2;
    }
}

// ---------------- grouped expert GEMM: single fp16 HMMA pass ----------------
#define ROW_B   144                      // 64 fp16 (128B) + 16B pad
#define MAT_B   (128 * ROW_B)            // 18432
#define STAGE_B (2 * MAT_B)              // 36864 (A, B)
#define GEMM_SMEM (3 * STAGE_B)          // 110592

__global__ void __launch_bounds__(256, 2) expert_gemm_mma(
    const float* __restrict__ bk, float* __restrict__ out)
{
    const int e   = blockIdx.x / TM_TILES;
    const int mt  = blockIdx.x % TM_TILES;
    const int cnt = g_count[e];
    const int m0  = mt * BM;
    if (m0 >= cnt) return;
    const int nb = blockIdx.y * BN;

    extern __shared__ char smem[];
    __shared__ int   sTok[BM];
    __shared__ float sGate[BM];

    const int tid = threadIdx.x, wid = tid >> 5, lane = tid & 31;
    const int warp_m = wid & 3, warp_n = wid >> 2;

    if (tid < BM) {
        int m = m0 + tid;
        bool v = (m < cnt);
        sTok[tid]  = v ? g_tok[e][m] : g_tok[e][m0];
        sGate[tid] = v ? g_gate[e][m] : 0.f;
    }
    __syncthreads();

    const uint32_t sb = smem_u32(smem);

    uint32_t stOff[4];
    size_t   aOff[4], bOff[4];
#pragma unroll
    for (int j = 0; j < 4; j++) {
        int unit = tid + 256 * j;             // 0..1023
        int row = unit >> 3, seg = unit & 7;
        stOff[j] = (uint32_t)(row * ROW_B + seg * 16);
        aOff[j] = (size_t)sTok[row] * DIM + seg * 8;
        bOff[j] = ((size_t)e * DIM + nb + row) * DIM + seg * 8;
    }

    const uint32_t aLd = (uint32_t)((warp_m * 32 + (lane & 15)) * ROW_B + (lane >> 4) * 16);
    const uint32_t bLd = (uint32_t)((warp_n * 64 + ((lane >> 4) * 8) + (lane & 7)) * ROW_B
                                    + ((lane >> 3) & 1) * 16);

    float acc[2][8][4];
#pragma unroll
    for (int i = 0; i < 2; i++)
#pragma unroll
        for (int t = 0; t < 8; t++)
#pragma unroll
            for (int q = 0; q < 4; q++) acc[i][t][q] = 0.f;

    auto load_stage = [&](int st) {
        const int k0 = st * BK;
        const uint32_t base = sb + (st % 3) * STAGE_B;
#pragma unroll
        for (int j = 0; j < 4; j++) {
            cp16(base + 0 * MAT_B + stOff[j], g_x  + aOff[j] + k0);
            cp16(base + 1 * MAT_B + stOff[j], g_wk + bOff[j] + k0);
        }
        cp_commit();
    };

    load_stage(0);
    load_stage(1);

#pragma unroll 1
    for (int st = 0; st < KSTAGES; st++) {
        if (st + 1 < KSTAGES) cp_wait<1>();
        else                  cp_wait<0>();
        __syncthreads();
        if (st + 2 < KSTAGES) load_stage(st + 2);

        const uint32_t base = sb + (st % 3) * STAGE_B;
        const uint32_t aB = base + 0 * MAT_B + aLd;
        const uint32_t bB = base + 1 * MAT_B + bLd;

#pragma unroll
        for (int kk = 0; kk < 4; kk++) {
            const uint32_t ko = kk * 32;
            uint32_t aF[2][4], bF[4][4];
#pragma unroll
            for (int i = 0; i < 2; i++)
                ldsm4(aF[i][0], aF[i][1], aF[i][2], aF[i][3], aB + i * 16 * ROW_B + ko);
#pragma unroll
            for (int p = 0; p < 4; p++)
                ldsm4(bF[p][0], bF[p][1], bF[p][2], bF[p][3], bB + p * 16 * ROW_B + ko);
#pragma unroll
            for (int i = 0; i < 2; i++)
#pragma unroll
                for (int p = 0; p < 4; p++)
#pragma unroll
                    for (int h = 0; h < 2; h++)
                        mma16816(acc[i][2 * p + h], aF[i], &bF[p][h * 2]);
        }
    }

    // ---------------- epilogue: red.global.add of gate*(acc+bk) -------------
    float2 bkf[8];
    {
        const float* bkp = bk + (size_t)e * DIM + nb + warp_n * 64 + (lane & 3) * 2;
#pragma unroll
        for (int t = 0; t < 8; t++) bkf[t] = *(const float2*)(bkp + t * 8);
    }
#pragma unroll
    for (int i = 0; i < 2; i++) {
#pragma unroll
        for (int half = 0; half < 2; half++) {
            const int mrow = warp_m * 32 + i * 16 + half * 8 + (lane >> 2);
            const int m = m0 + mrow;
            if (m < cnt) {
                const int   tok = sTok[mrow];
                const float g   = sGate[mrow];
                float* op = out + (size_t)tok * DIM + nb + warp_n * 64 + (lane & 3) * 2;
#pragma unroll
                for (int t = 0; t < 8; t++) {
                    redf(op + t * 8 + 0, g * (acc[i][t][half * 2 + 0] + bkf[t].x));
                    redf(op + t * 8 + 1, g * (acc[i][t][half * 2 + 1] + bkf[t].y));
                }
            }
        }
    }
}

// ---------------- launch -----------------------------------------------------
extern "C" void kernel_launch(void* const* d_in, const int* in_sizes, int n_in,
                              void* d_out, int out_size) {
    const float* x   = (const float*)d_in[0];
    const float* eps = (const float*)d_in[1];
    const float* Wr  = (const float*)d_in[2];
    const float* br  = (const float*)d_in[3];
    const float* Wn  = (const float*)d_in[4];
    const float* bn  = (const float*)d_in[5];
    const float* Wk  = (const float*)d_in[6];
    const float* bk  = (const float*)d_in[7];
    float* out = (float*)d_out;

    cudaFuncSetAttribute(expert_gemm_mma,
                         cudaFuncAttributeMaxDynamicSharedMemorySize, GEMM_SMEM);

    init_counts_kernel<<<1, 32>>>();
    zero_out_kernel<<<(NTOK * DIM / 4) / 256, 256>>>(out);
    convert_x_kernel<<<(NTOK * DIM / 4) / 256, 256>>>(x);
    convert_wk_kernel<<<dim3(8, 8, 8), 256>>>(Wk);
    router_kernel<<<NTOK / 32, 256>>>(x, eps, Wr, br, Wn, bn);
    dim3 ggrid(NEXP * TM_TILES, DIM / BN);
    expert_gemm_mma<<<ggrid, 256, GEMM_SMEM>>>(bk, out);
}

// round 9
// speedup vs baseline: 2.7859x; 1.0141x over previous
#include <cuda_runtime.h>
#include <cuda_fp16.h>
#include <math.h>
#include <stdint.h>

#define NTOK  16384
#define DIM   512
#define NEXP  8
#define BM    128
#define BN    128
#define BK    64
#define KSTAGES (DIM / BK)          // 8
#define GEMM_GRID 296               // 2 CTAs x 148 SMs

// ---------------- static device scratch ------------------------------------
__device__ int     g_count[NEXP];
__device__ int     g_tok [NEXP][NTOK];
__device__ float   g_gate[NEXP][NTOK];
__device__ __half  g_x  [NTOK * DIM];               // fp16 x
__device__ __half  g_wk [NEXP * DIM * DIM];         // [e][n][k] fp16

// ---------------- helpers ---------------------------------------------------
__device__ __forceinline__ uint32_t smem_u32(const void* p) {
    uint32_t a;
    asm("{ .reg .u64 t; cvta.to.shared.u64 t, %1; cvt.u32.u64 %0, t; }" : "=r"(a) : "l"(p));
    return a;
}
__device__ __forceinline__ void cp16(uint32_t saddr, const void* g) {
    asm volatile("cp.async.cg.shared.global [%0], [%1], 16;" :: "r"(saddr), "l"(g));
}
__device__ __forceinline__ void cp_commit() { asm volatile("cp.async.commit_group;"); }
template<int N> __device__ __forceinline__ void cp_wait() {
    asm volatile("cp.async.wait_group %0;" :: "n"(N));
}
__device__ __forceinline__ void ldsm4(uint32_t& r0, uint32_t& r1, uint32_t& r2, uint32_t& r3,
                                      uint32_t addr) {
    asm volatile("ldmatrix.sync.aligned.m8n8.x4.shared.b16 {%0,%1,%2,%3}, [%4];"
                 : "=r"(r0), "=r"(r1), "=r"(r2), "=r"(r3) : "r"(addr));
}
__device__ __forceinline__ void mma16816(float* c, const uint32_t* a, const uint32_t* b) {
    asm volatile(
        "mma.sync.aligned.m16n8k16.row.col.f32.f16.f16.f32 "
        "{%0,%1,%2,%3}, {%4,%5,%6,%7}, {%8,%9}, {%0,%1,%2,%3};"
        : "+f"(c[0]), "+f"(c[1]), "+f"(c[2]), "+f"(c[3])
        : "r"(a[0]), "r"(a[1]), "r"(a[2]), "r"(a[3]), "r"(b[0]), "r"(b[1]));
}
__device__ __forceinline__ void redf(float* p, float v) {
    asm volatile("red.global.add.f32 [%0], %1;" :: "l"(p), "f"(v) : "memory");
}

// ---------------- prep: zero out + counters, Wk transpose+fp16 ---------------
// blocks [0,512): Wk [e][k][n] fp32 -> [e][n][k] fp16
// blocks [512, 512+8192): zero 16384x512 fp32 out (float4 per thread)
__global__ void __launch_bounds__(256) prep_kernel(
    const float* __restrict__ Wk, float* __restrict__ out)
{
    const int tid = threadIdx.x;
    if (blockIdx.x >= 512) {
        const size_t i = (size_t)(blockIdx.x - 512) * 256 + tid;
        ((float4*)out)[i] = make_float4(0.f, 0.f, 0.f, 0.f);
        if (blockIdx.x == 512 && tid < NEXP) g_count[tid] = 0;
        return;
    }
    __shared__ float s[64][65];
    const int b = blockIdx.x;             // 0..511 = e(3b) x kt(3b) x nt(3b)? 8*8*8
    const int e = b >> 6, kt = ((b >> 3) & 7) * 64, nt = (b & 7) * 64;
    const float* src = Wk + ((size_t)e * DIM + kt) * DIM + nt;
#pragma unroll
    for (int j = 0; j < 4; j++) {
        int unit = tid + 256 * j;
        int kr = unit >> 4, nc = (unit & 15) * 4;
        float4 v = *(const float4*)(src + (size_t)kr * DIM + nc);
        s[kr][nc + 0] = v.x; s[kr][nc + 1] = v.y;
        s[kr][nc + 2] = v.z; s[kr][nc + 3] = v.w;
    }
    __syncthreads();
    __half* dh = g_wk + ((size_t)e * DIM + nt) * DIM + kt;
#pragma unroll
    for (int j = 0; j < 4; j++) {
        int unit = tid + 256 * j;
        int nr = unit >> 4, kq = (unit & 15) * 4;
        __half2 p0 = __floats2half2_rn(s[kq + 0][nr], s[kq + 1][nr]);
        __half2 p1 = __floats2half2_rn(s[kq + 2][nr], s[kq + 3][nr]);
        *(uint2*)(dh + (size_t)nr * DIM + kq) =
            make_uint2(*(uint32_t*)&p0, *(uint32_t*)&p1);
    }
}

// ---------------- router + x->fp16 convert (fused) ---------------------------
// 4 tokens/warp, 8 lanes/token; each lane holds 16 float4 = the full row slice,
// converts it to fp16 while it's in registers.
__global__ void __launch_bounds__(256) router_kernel(
    const float* __restrict__ x,   const float* __restrict__ eps,
    const float* __restrict__ Wr,  const float* __restrict__ br,
    const float* __restrict__ Wn,  const float* __restrict__ bn)
{
    __shared__ float4 sWr4[NEXP][DIM / 4];
    __shared__ float4 sWn4[NEXP][DIM / 4];
    const int tid = threadIdx.x;
    {
        float* pr = (float*)sWr4;
        float* pn = (float*)sWn4;
        for (int i = tid; i < DIM * NEXP; i += 256) {
            int d = i >> 3, e = i & 7;
            pr[e * DIM + d] = Wr[i];
            pn[e * DIM + d] = Wn[i];
        }
    }
    __syncthreads();

    const int warp = tid >> 5, lane = tid & 31;
    const int grp = lane >> 3, sl = lane & 7;
    const int t = blockIdx.x * 32 + warp * 4 + grp;

    const float4* xr = (const float4*)(x + (size_t)t * DIM);
    float4 xf[16];
#pragma unroll
    for (int i = 0; i < 16; i++) xf[i] = xr[sl + 8 * i];

    // emit fp16 copy while the row is in registers
    {
        uint2* xo = (uint2*)(g_x + (size_t)t * DIM);
#pragma unroll
        for (int i = 0; i < 16; i++) {
            __half2 p0 = __floats2half2_rn(xf[i].x, xf[i].y);
            __half2 p1 = __floats2half2_rn(xf[i].z, xf[i].w);
            xo[sl + 8 * i] = make_uint2(*(uint32_t*)&p0, *(uint32_t*)&p1);
        }
    }

    float noisy[NEXP];
#pragma unroll
    for (int e = 0; e < NEXP; e++) {
        float ar = 0.f, an = 0.f;
#pragma unroll
        for (int i = 0; i < 16; i++) {
            float4 wr = sWr4[e][sl + 8 * i];
            float4 wn = sWn4[e][sl + 8 * i];
            ar = fmaf(xf[i].x, wr.x, ar); ar = fmaf(xf[i].y, wr.y, ar);
            ar = fmaf(xf[i].z, wr.z, ar); ar = fmaf(xf[i].w, wr.w, ar);
            an = fmaf(xf[i].x, wn.x, an); an = fmaf(xf[i].y, wn.y, an);
            an = fmaf(xf[i].z, wn.z, an); an = fmaf(xf[i].w, wn.w, an);
        }
#pragma unroll
        for (int o = 4; o; o >>= 1) {
            ar += __shfl_xor_sync(0xffffffffu, ar, o);
            an += __shfl_xor_sync(0xffffffffu, an, o);
        }
        float lg = ar + br[e];
        float nl = an + bn[e];
        float sp = fmaxf(nl, 0.f) + log1pf(expf(-fabsf(nl)));
        noisy[e] = lg + eps[(size_t)t * NEXP + e] * sp;
    }

    if (sl == 0) {
        int i1 = 0; float v1 = noisy[0];
#pragma unroll
        for (int e = 1; e < NEXP; e++) if (noisy[e] > v1) { v1 = noisy[e]; i1 = e; }
        int i2 = -1; float v2 = -INFINITY;
#pragma unroll
        for (int e = 0; e < NEXP; e++) if (e != i1 && noisy[e] > v2) { v2 = noisy[e]; i2 = e; }
        float ex = expf(v2 - v1);
        float inv = 1.f / (1.f + ex);
        float g1 = inv, g2 = ex * inv;

        int p1 = atomicAdd(&g_count[i1], 1);
        g_tok[i1][p1] = t; g_gate[i1][p1] = g1;
        int p2 = atomicAdd(&g_count[i2], 1);
        g_tok[i2][p2] = t; g_gate[i2][p2] = g2;
    }
}

// ---------------- persistent grouped expert GEMM (fp16 HMMA) ----------------
#define ROW_B   144
#define MAT_B   (128 * ROW_B)            // 18432
#define STAGE_B (2 * MAT_B)              // 36864
#define GEMM_SMEM (3 * STAGE_B)          // 110592

__global__ void __launch_bounds__(256, 2) expert_gemm_mma(
    const float* __restrict__ bk, float* __restrict__ out)
{
    // per-CTA identical tile table from g_count (deterministic static schedule)
    int off[NEXP + 1];
    off[0] = 0;
#pragma unroll
    for (int e = 0; e < NEXP; e++)
        off[e + 1] = off[e] + ((g_count[e] + BM - 1) >> 7);
    const int total = off[NEXP] * 4;

    extern __shared__ char smem[];
    __shared__ int   sTok[BM];
    __shared__ float sGate[BM];

    const int tid = threadIdx.x, wid = tid >> 5, lane = tid & 31;
    const int warp_m = wid & 3, warp_n = wid >> 2;
    const uint32_t sb = smem_u32(smem);

    const uint32_t aLd = (uint32_t)((warp_m * 32 + (lane & 15)) * ROW_B + (lane >> 4) * 16);
    const uint32_t bLd = (uint32_t)((warp_n * 64 + ((lane >> 4) * 8) + (lane & 7)) * ROW_B
                                    + ((lane >> 3) & 1) * 16);

#pragma unroll 1
    for (int work = blockIdx.x; work < total; work += GEMM_GRID) {
        const int rt = work >> 2;
        const int nb = (work & 3) << 7;
        int e = 0;
#pragma unroll
        for (int q = 0; q < NEXP - 1; q++) if (rt >= off[q + 1]) e = q + 1;
        const int mt  = rt - off[e];
        const int cnt = g_count[e];
        const int m0  = mt * BM;

        __syncthreads();                    // protect sTok/smem reuse across tiles
        if (tid < BM) {
            int m = m0 + tid;
            bool v = (m < cnt);
            sTok[tid]  = v ? g_tok[e][m] : g_tok[e][m0];
            sGate[tid] = v ? g_gate[e][m] : 0.f;
        }
        __syncthreads();

        uint32_t stOff[4];
        size_t   aOff[4], bOff[4];
#pragma unroll
        for (int j = 0; j < 4; j++) {
            int unit = tid + 256 * j;
            int row = unit >> 3, seg = unit & 7;
            stOff[j] = (uint32_t)(row * ROW_B + seg * 16);
            aOff[j] = (size_t)sTok[row] * DIM + seg * 8;
            bOff[j] = ((size_t)e * DIM + nb + row) * DIM + seg * 8;
        }

        float acc[2][8][4];
#pragma unroll
        for (int i = 0; i < 2; i++)
#pragma unroll
            for (int t = 0; t < 8; t++)
#pragma unroll
                for (int q = 0; q < 4; q++) acc[i][t][q] = 0.f;

        auto load_stage = [&](int st) {
            const int k0 = st * BK;
            const uint32_t base = sb + (st % 3) * STAGE_B;
#pragma unroll
            for (int j = 0; j < 4; j++) {
                cp16(base + 0 * MAT_B + stOff[j], g_x  + aOff[j] + k0);
                cp16(base + 1 * MAT_B + stOff[j], g_wk + bOff[j] + k0);
            }
            cp_commit();
        };

        load_stage(0);
        load_stage(1);

#pragma unroll 1
        for (int st = 0; st < KSTAGES; st++) {
            if (st + 1 < KSTAGES) cp_wait<1>();
            else                  cp_wait<0>();
            __syncthreads();
            if (st + 2 < KSTAGES) load_stage(st + 2);

            const uint32_t base = sb + (st % 3) * STAGE_B;
            const uint32_t aB = base + 0 * MAT_B + aLd;
            const uint32_t bB = base + 1 * MAT_B + bLd;

#pragma unroll
            for (int kk = 0; kk < 4; kk++) {
                const uint32_t ko = kk * 32;
                uint32_t aF[2][4], bF[4][4];
#pragma unroll
                for (int i = 0; i < 2; i++)
                    ldsm4(aF[i][0], aF[i][1], aF[i][2], aF[i][3], aB + i * 16 * ROW_B + ko);
#pragma unroll
                for (int p = 0; p < 4; p++)
                    ldsm4(bF[p][0], bF[p][1], bF[p][2], bF[p][3], bB + p * 16 * ROW_B + ko);
#pragma unroll
                for (int i = 0; i < 2; i++)
#pragma unroll
                    for (int p = 0; p < 4; p++)
#pragma unroll
                        for (int h = 0; h < 2; h++)
                            mma16816(acc[i][2 * p + h], aF[i], &bF[p][h * 2]);
            }
        }

        // epilogue: red.global.add of gate*(acc+bk)
        float2 bkf[8];
        {
            const float* bkp = bk + (size_t)e * DIM + nb + warp_n * 64 + (lane & 3) * 2;
#pragma unroll
            for (int t = 0; t < 8; t++) bkf[t] = *(const float2*)(bkp + t * 8);
        }
#pragma unroll
        for (int i = 0; i < 2; i++) {
#pragma unroll
            for (int half = 0; half < 2; half++) {
                const int mrow = warp_m * 32 + i * 16 + half * 8 + (lane >> 2);
                const int m = m0 + mrow;
                if (m < cnt) {
                    const int   tok = sTok[mrow];
                    const float g   = sGate[mrow];
                    float* op = out + (size_t)tok * DIM + nb + warp_n * 64 + (lane & 3) * 2;
#pragma unroll
                    for (int t = 0; t < 8; t++) {
                        redf(op + t * 8 + 0, g * (acc[i][t][half * 2 + 0] + bkf[t].x));
                        redf(op + t * 8 + 1, g * (acc[i][t][half * 2 + 1] + bkf[t].y));
                    }
                }
            }
        }
    }
}

// ---------------- launch -----------------------------------------------------
extern "C" void kernel_launch(void* const* d_in, const int* in_sizes, int n_in,
                              void* d_out, int out_size) {
    const float* x   = (const float*)d_in[0];
    const float* eps = (const float*)d_in[1];
    const float* Wr  = (const float*)d_in[2];
    const float* br  = (const float*)d_in[3];
    const float* Wn  = (const float*)d_in[4];
    const float* bn  = (const float*)d_in[5];
    const float* Wk  = (const float*)d_in[6];
    const float* bk  = (const float*)d_in[7];
    float* out = (float*)d_out;

    cudaFuncSetAttribute(expert_gemm_mma,
                         cudaFuncAttributeMaxDynamicSharedMemorySize, GEMM_SMEM);

    prep_kernel<<<512 + (NTOK * DIM / 4) / 256, 256>>>(Wk, out);
    router_kernel<<<NTOK / 32, 256>>>(x, eps, Wr, br, Wn, bn);
    expert_gemm_mma<<<GEMM_GRID, 256, GEMM_SMEM>>>(bk, out);
}

// round 10
// speedup vs baseline: 3.2520x; 1.1673x over previous
#include <cuda_runtime.h>
#include <cuda_fp16.h>
#include <math.h>
#include <stdint.h>

#define NTOK  16384
#define DIM   512
#define NEXP  8
#define BM    128
#define BN    128
#define BK    64
#define KSTAGES (DIM / BK)          // 8
#define GEMM_GRID 296               // 2 CTAs x 148 SMs

// ---------------- static device scratch ------------------------------------
__device__ int     g_count[NEXP];
__device__ int     g_tok [NEXP][NTOK];
__device__ float   g_gate[NEXP][NTOK];
__device__ __half  g_x  [NTOK * DIM];
__device__ __half  g_wk [NEXP * DIM * DIM];         // [e][n][k] fp16

// ---------------- helpers ---------------------------------------------------
__device__ __forceinline__ uint32_t smem_u32(const void* p) {
    uint32_t a;
    asm("{ .reg .u64 t; cvta.to.shared.u64 t, %1; cvt.u32.u64 %0, t; }" : "=r"(a) : "l"(p));
    return a;
}
__device__ __forceinline__ void cp16(uint32_t saddr, const void* g) {
    asm volatile("cp.async.cg.shared.global [%0], [%1], 16;" :: "r"(saddr), "l"(g));
}
__device__ __forceinline__ void cp_commit() { asm volatile("cp.async.commit_group;"); }
template<int N> __device__ __forceinline__ void cp_wait() {
    asm volatile("cp.async.wait_group %0;" :: "n"(N));
}
__device__ __forceinline__ void ldsm4(uint32_t& r0, uint32_t& r1, uint32_t& r2, uint32_t& r3,
                                      uint32_t addr) {
    asm volatile("ldmatrix.sync.aligned.m8n8.x4.shared.b16 {%0,%1,%2,%3}, [%4];"
                 : "=r"(r0), "=r"(r1), "=r"(r2), "=r"(r3) : "r"(addr));
}
__device__ __forceinline__ void mma16816(float* c, const uint32_t* a, const uint32_t* b) {
    asm volatile(
        "mma.sync.aligned.m16n8k16.row.col.f32.f16.f16.f32 "
        "{%0,%1,%2,%3}, {%4,%5,%6,%7}, {%8,%9}, {%0,%1,%2,%3};"
        : "+f"(c[0]), "+f"(c[1]), "+f"(c[2]), "+f"(c[3])
        : "r"(a[0]), "r"(a[1]), "r"(a[2]), "r"(a[3]), "r"(b[0]), "r"(b[1]));
}
__device__ __forceinline__ void redf2(float* p, float a, float b) {
    asm volatile("red.global.add.v2.f32 [%0], {%1, %2};"
                 :: "l"(p), "f"(a), "f"(b) : "memory");
}

// ---------------- prep: zero out + counters, Wk transpose+fp16 ---------------
__global__ void __launch_bounds__(256) prep_kernel(
    const float* __restrict__ Wk, float* __restrict__ out)
{
    const int tid = threadIdx.x;
    if (blockIdx.x >= 512) {
        const size_t i = (size_t)(blockIdx.x - 512) * 256 + tid;
        ((float4*)out)[i] = make_float4(0.f, 0.f, 0.f, 0.f);
        if (blockIdx.x == 512 && tid < NEXP) g_count[tid] = 0;
        return;
    }
    __shared__ float s[64][65];
    const int b = blockIdx.x;
    const int e = b >> 6, kt = ((b >> 3) & 7) * 64, nt = (b & 7) * 64;
    const float* src = Wk + ((size_t)e * DIM + kt) * DIM + nt;
#pragma unroll
    for (int j = 0; j < 4; j++) {
        int unit = tid + 256 * j;
        int kr = unit >> 4, nc = (unit & 15) * 4;
        float4 v = *(const float4*)(src + (size_t)kr * DIM + nc);
        s[kr][nc + 0] = v.x; s[kr][nc + 1] = v.y;
        s[kr][nc + 2] = v.z; s[kr][nc + 3] = v.w;
    }
    __syncthreads();
    __half* dh = g_wk + ((size_t)e * DIM + nt) * DIM + kt;
#pragma unroll
    for (int j = 0; j < 4; j++) {
        int unit = tid + 256 * j;
        int nr = unit >> 4, kq = (unit & 15) * 4;
        __half2 p0 = __floats2half2_rn(s[kq + 0][nr], s[kq + 1][nr]);
        __half2 p1 = __floats2half2_rn(s[kq + 2][nr], s[kq + 3][nr]);
        *(uint2*)(dh + (size_t)nr * DIM + kq) =
            make_uint2(*(uint32_t*)&p0, *(uint32_t*)&p1);
    }
}

// ---------------- router + x->fp16 convert (fused, proven) -------------------
__global__ void __launch_bounds__(256) router_kernel(
    const float* __restrict__ x,   const float* __restrict__ eps,
    const float* __restrict__ Wr,  const float* __restrict__ br,
    const float* __restrict__ Wn,  const float* __restrict__ bn)
{
    __shared__ float4 sWr4[NEXP][DIM / 4];
    __shared__ float4 sWn4[NEXP][DIM / 4];
    const int tid = threadIdx.x;
    {
        float* pr = (float*)sWr4;
        float* pn = (float*)sWn4;
        for (int i = tid; i < DIM * NEXP; i += 256) {
            int d = i >> 3, e = i & 7;
            pr[e * DIM + d] = Wr[i];
            pn[e * DIM + d] = Wn[i];
        }
    }
    __syncthreads();

    const int warp = tid >> 5, lane = tid & 31;
    const int grp = lane >> 3, sl = lane & 7;
    const int t = blockIdx.x * 32 + warp * 4 + grp;

    const float4* xr = (const float4*)(x + (size_t)t * DIM);
    float4 xf[16];
#pragma unroll
    for (int i = 0; i < 16; i++) xf[i] = xr[sl + 8 * i];

    {
        uint2* xo = (uint2*)(g_x + (size_t)t * DIM);
#pragma unroll
        for (int i = 0; i < 16; i++) {
            __half2 p0 = __floats2half2_rn(xf[i].x, xf[i].y);
            __half2 p1 = __floats2half2_rn(xf[i].z, xf[i].w);
            xo[sl + 8 * i] = make_uint2(*(uint32_t*)&p0, *(uint32_t*)&p1);
        }
    }

    float noisy[NEXP];
#pragma unroll
    for (int e = 0; e < NEXP; e++) {
        float ar = 0.f, an = 0.f;
#pragma unroll
        for (int i = 0; i < 16; i++) {
            float4 wr = sWr4[e][sl + 8 * i];
            float4 wn = sWn4[e][sl + 8 * i];
            ar = fmaf(xf[i].x, wr.x, ar); ar = fmaf(xf[i].y, wr.y, ar);
            ar = fmaf(xf[i].z, wr.z, ar); ar = fmaf(xf[i].w, wr.w, ar);
            an = fmaf(xf[i].x, wn.x, an); an = fmaf(xf[i].y, wn.y, an);
            an = fmaf(xf[i].z, wn.z, an); an = fmaf(xf[i].w, wn.w, an);
        }
#pragma unroll
        for (int o = 4; o; o >>= 1) {
            ar += __shfl_xor_sync(0xffffffffu, ar, o);
            an += __shfl_xor_sync(0xffffffffu, an, o);
        }
        float lg = ar + br[e];
        float nl = an + bn[e];
        float sp = fmaxf(nl, 0.f) + log1pf(expf(-fabsf(nl)));
        noisy[e] = lg + eps[(size_t)t * NEXP + e] * sp;
    }

    if (sl == 0) {
        int i1 = 0; float v1 = noisy[0];
#pragma unroll
        for (int e = 1; e < NEXP; e++) if (noisy[e] > v1) { v1 = noisy[e]; i1 = e; }
        int i2 = -1; float v2 = -INFINITY;
#pragma unroll
        for (int e = 0; e < NEXP; e++) if (e != i1 && noisy[e] > v2) { v2 = noisy[e]; i2 = e; }
        float ex = expf(v2 - v1);
        float inv = 1.f / (1.f + ex);
        float g1 = inv, g2 = ex * inv;

        int p1 = atomicAdd(&g_count[i1], 1);
        g_tok[i1][p1] = t; g_gate[i1][p1] = g1;
        int p2 = atomicAdd(&g_count[i2], 1);
        g_tok[i2][p2] = t; g_gate[i2][p2] = g2;
    }
}

// ---------------- persistent GEMM, cross-tile pipelined ---------------------
#define ROW_B   144
#define MAT_B   (128 * ROW_B)            // 18432
#define STAGE_B (2 * MAT_B)              // 36864
#define GEMM_SMEM (3 * STAGE_B)          // 110592

__global__ void __launch_bounds__(256, 2) expert_gemm_mma(
    const float* __restrict__ bk, float* __restrict__ out)
{
    int off[NEXP + 1];
    off[0] = 0;
#pragma unroll
    for (int e = 0; e < NEXP; e++)
        off[e + 1] = off[e] + ((g_count[e] + BM - 1) >> 7);
    const int total = off[NEXP] * 4;

    extern __shared__ char smem[];
    __shared__ int   sTok [2][BM];
    __shared__ float sGate[2][BM];

    const int tid = threadIdx.x, wid = tid >> 5, lane = tid & 31;
    const int warp_m = wid & 3, warp_n = wid >> 2;
    const uint32_t sb = smem_u32(smem);

    const uint32_t aLd = (uint32_t)((warp_m * 32 + (lane & 15)) * ROW_B + (lane >> 4) * 16);
    const uint32_t bLd = (uint32_t)((warp_n * 64 + ((lane >> 4) * 8) + (lane & 7)) * ROW_B
                                    + ((lane >> 3) & 1) * 16);
    uint32_t stOff[4];
#pragma unroll
    for (int j = 0; j < 4; j++) {
        int unit = tid + 256 * j;
        stOff[j] = (uint32_t)((unit >> 3) * ROW_B + (unit & 7) * 16);
    }

    auto decode = [&](int w, int& de, int& dm0, int& dnb, int& dcnt) {
        int rt = w >> 2;
        dnb = (w & 3) << 7;
        int q = 0;
#pragma unroll
        for (int u = 0; u < NEXP - 1; u++) if (rt >= off[u + 1]) q = u + 1;
        de = q;
        dm0 = (rt - off[q]) * BM;
        dcnt = g_count[q];
    };
    auto calc_offs = [&](int e_, int nb_, const int* tokArr, uint32_t* aO, uint32_t* bO) {
#pragma unroll
        for (int j = 0; j < 4; j++) {
            int unit = tid + 256 * j;
            int row = unit >> 3, seg = unit & 7;
            aO[j] = (uint32_t)(tokArr[row] * DIM + seg * 8);
            bO[j] = (uint32_t)(((e_ * DIM) + nb_ + row) * DIM + seg * 8);
        }
    };
    auto issue = [&](int slot, int k0, const uint32_t* aO, const uint32_t* bO) {
        const uint32_t base = sb + slot * STAGE_B;
#pragma unroll
        for (int j = 0; j < 4; j++) {
            cp16(base + 0 * MAT_B + stOff[j], g_x  + aO[j] + k0);
            cp16(base + 1 * MAT_B + stOff[j], g_wk + bO[j] + k0);
        }
        cp_commit();
    };

    int work = blockIdx.x;
    if (work >= total) return;

    int e, m0, nb, cnt;
    decode(work, e, m0, nb, cnt);
    int p = 0;
    if (tid < BM) {
        int m = m0 + tid;
        bool v = (m < cnt);
        sTok [p][tid] = v ? g_tok[e][m] : g_tok[e][m0];
        sGate[p][tid] = v ? g_gate[e][m] : 0.f;
    }
    __syncthreads();

    uint32_t aOff[4], bOff[4];
    calc_offs(e, nb, sTok[p], aOff, bOff);
    int slotBase = 0;
    issue(0, 0, aOff, bOff);
    issue(1, BK, aOff, bOff);

#pragma unroll 1
    while (true) {
        const int nwork = work + GEMM_GRID;
        const bool hasNext = (nwork < total);
        int e2 = 0, m02 = 0, nb2 = 0, cnt2 = 0;
        __syncthreads();          // epilogue of prev tile done before sTok[p^1] reuse
        if (hasNext) {
            decode(nwork, e2, m02, nb2, cnt2);
            if (tid < BM) {
                int m = m02 + tid;
                bool v = (m < cnt2);
                sTok [p ^ 1][tid] = v ? g_tok[e2][m] : g_tok[e2][m02];
                sGate[p ^ 1][tid] = v ? g_gate[e2][m] : 0.f;
            }
        }

        float acc[2][8][4];
#pragma unroll
        for (int i = 0; i < 2; i++)
#pragma unroll
            for (int t = 0; t < 8; t++)
#pragma unroll
                for (int q = 0; q < 4; q++) acc[i][t][q] = 0.f;

        uint32_t aOff2[4], bOff2[4];

#pragma unroll 1
        for (int st = 0; st < KSTAGES; st++) {
            if (st == KSTAGES - 1 && !hasNext) cp_wait<0>();
            else                               cp_wait<1>();
            __syncthreads();
            if (st + 2 < KSTAGES) {
                issue((slotBase + st + 2) % 3, (st + 2) * BK, aOff, bOff);
            } else if (hasNext) {
                const int nst = st + 2 - KSTAGES;     // 0 or 1
                if (nst == 0) calc_offs(e2, nb2, sTok[p ^ 1], aOff2, bOff2);
                issue((slotBase + st + 2) % 3, nst * BK, aOff2, bOff2);
            }

            const uint32_t base = sb + ((slotBase + st) % 3) * STAGE_B;
            const uint32_t aB = base + 0 * MAT_B + aLd;
            const uint32_t bB = base + 1 * MAT_B + bLd;
#pragma unroll
            for (int kk = 0; kk < 4; kk++) {
                const uint32_t ko = kk * 32;
                uint32_t aF[2][4], bF[4][4];
#pragma unroll
                for (int i = 0; i < 2; i++)
                    ldsm4(aF[i][0], aF[i][1], aF[i][2], aF[i][3], aB + i * 16 * ROW_B + ko);
#pragma unroll
                for (int q = 0; q < 4; q++)
                    ldsm4(bF[q][0], bF[q][1], bF[q][2], bF[q][3], bB + q * 16 * ROW_B + ko);
#pragma unroll
                for (int i = 0; i < 2; i++)
#pragma unroll
                    for (int q = 0; q < 4; q++)
#pragma unroll
                        for (int h = 0; h < 2; h++)
                            mma16816(acc[i][2 * q + h], aF[i], &bF[q][h * 2]);
            }
        }

        // epilogue: vectorized red.global.add of gate*(acc+bk); overlaps the
        // next tile's stage-0/1 cp.asyncs issued above.
        {
            float2 bkf[8];
            const float* bkp = bk + (size_t)e * DIM + nb + warp_n * 64 + (lane & 3) * 2;
#pragma unroll
            for (int t = 0; t < 8; t++) bkf[t] = *(const float2*)(bkp + t * 8);
#pragma unroll
            for (int i = 0; i < 2; i++) {
#pragma unroll
                for (int half = 0; half < 2; half++) {
                    const int mrow = warp_m * 32 + i * 16 + half * 8 + (lane >> 2);
                    const int m = m0 + mrow;
                    if (m < cnt) {
                        const int   tok = sTok [p][mrow];
                        const float g   = sGate[p][mrow];
                        float* op = out + (size_t)tok * DIM + nb + warp_n * 64 + (lane & 3) * 2;
#pragma unroll
                        for (int t = 0; t < 8; t++)
                            redf2(op + t * 8,
                                  g * (acc[i][t][half * 2 + 0] + bkf[t].x),
                                  g * (acc[i][t][half * 2 + 1] + bkf[t].y));
                    }
                }
            }
        }

        if (!hasNext) break;
        work = nwork;
        e = e2; m0 = m02; nb = nb2; cnt = cnt2;
#pragma unroll
        for (int j = 0; j < 4; j++) { aOff[j] = aOff2[j]; bOff[j] = bOff2[j]; }
        p ^= 1;
        slotBase = (slotBase + KSTAGES) % 3;
    }
}

// ---------------- launch -----------------------------------------------------
extern "C" void kernel_launch(void* const* d_in, const int* in_sizes, int n_in,
                              void* d_out, int out_size) {
    const float* x   = (const float*)d_in[0];
    const float* eps = (const float*)d_in[1];
    const float* Wr  = (const float*)d_in[2];
    const float* br  = (const float*)d_in[3];
    const float* Wn  = (const float*)d_in[4];
    const float* bn  = (const float*)d_in[5];
    const float* Wk  = (const float*)d_in[6];
    const float* bk  = (const float*)d_in[7];
    float* out = (float*)d_out;

    cudaFuncSetAttribute(expert_gemm_mma,
                         cudaFuncAttributeMaxDynamicSharedMemorySize, GEMM_SMEM);

    prep_kernel<<<512 + (NTOK * DIM / 4) / 256, 256>>>(Wk, out);
    router_kernel<<<NTOK / 32, 256>>>(x, eps, Wr, br, Wn, bn);
    expert_gemm_mma<<<GEMM_GRID, 256, GEMM_SMEM>>>(bk, out);
}

// round 11
// speedup vs baseline: 3.3916x; 1.0429x over previous
#include <cuda_runtime.h>
#include <cuda_fp16.h>
#include <math.h>
#include <stdint.h>

#define NTOK  16384
#define DIM   512
#define NEXP  8
#define BM    128
#define BN    128
#define BK    64
#define KSTAGES (DIM / BK)          // 8
#define GEMM_GRID 296               // 2 CTAs x 148 SMs

// ---------------- static device scratch ------------------------------------
__device__ int     g_count[NEXP];
__device__ int     g_ticket;
__device__ int     g_tok [NEXP][NTOK];
__device__ float   g_gate[NEXP][NTOK];
__device__ __half  g_x  [NTOK * DIM];
__device__ __half  g_wk [NEXP * DIM * DIM];         // [e][n][k] fp16

// ---------------- helpers ---------------------------------------------------
__device__ __forceinline__ uint32_t smem_u32(const void* p) {
    uint32_t a;
    asm("{ .reg .u64 t; cvta.to.shared.u64 t, %1; cvt.u32.u64 %0, t; }" : "=r"(a) : "l"(p));
    return a;
}
__device__ __forceinline__ void cp16(uint32_t saddr, const void* g) {
    asm volatile("cp.async.cg.shared.global [%0], [%1], 16;" :: "r"(saddr), "l"(g));
}
__device__ __forceinline__ void cp_commit() { asm volatile("cp.async.commit_group;"); }
template<int N> __device__ __forceinline__ void cp_wait() {
    asm volatile("cp.async.wait_group %0;" :: "n"(N));
}
__device__ __forceinline__ void ldsm4(uint32_t& r0, uint32_t& r1, uint32_t& r2, uint32_t& r3,
                                      uint32_t addr) {
    asm volatile("ldmatrix.sync.aligned.m8n8.x4.shared.b16 {%0,%1,%2,%3}, [%4];"
                 : "=r"(r0), "=r"(r1), "=r"(r2), "=r"(r3) : "r"(addr));
}
__device__ __forceinline__ void mma16816(float* c, const uint32_t* a, const uint32_t* b) {
    asm volatile(
        "mma.sync.aligned.m16n8k16.row.col.f32.f16.f16.f32 "
        "{%0,%1,%2,%3}, {%4,%5,%6,%7}, {%8,%9}, {%0,%1,%2,%3};"
        : "+f"(c[0]), "+f"(c[1]), "+f"(c[2]), "+f"(c[3])
        : "r"(a[0]), "r"(a[1]), "r"(a[2]), "r"(a[3]), "r"(b[0]), "r"(b[1]));
}
__device__ __forceinline__ void redf2(float* p, float a, float b) {
    asm volatile("red.global.add.v2.f32 [%0], {%1, %2};"
                 :: "l"(p), "f"(a), "f"(b) : "memory");
}

// ---------------- init: counters + ticket (must precede router atomics) -----
__global__ void init_kernel() {
    if (threadIdx.x < NEXP) g_count[threadIdx.x] = 0;
    if (threadIdx.x == NEXP) g_ticket = 0;
}

// ---------------- fused prep + router ---------------------------------------
// blocks [0,512):      router (32 tokens each) + x->fp16 convert
// blocks [512,1024):   Wk [e][k][n] fp32 -> [e][n][k] fp16 transpose
// blocks [1024,9216):  zero out
__global__ void __launch_bounds__(256) fused_prep_router(
    const float* __restrict__ x,   const float* __restrict__ eps,
    const float* __restrict__ Wr,  const float* __restrict__ br,
    const float* __restrict__ Wn,  const float* __restrict__ bn,
    const float* __restrict__ Wk,  float* __restrict__ out)
{
    __shared__ union SU {
        float4 w[2][NEXP][DIM / 4];   // 32 KB (router)
        float  s[64][65];             // 16.9 KB (wk transpose)
    } u;
    const int tid = threadIdx.x;

    if (blockIdx.x >= 1024) {                      // ---- zero out ----
        const size_t i = (size_t)(blockIdx.x - 1024) * 256 + tid;
        ((float4*)out)[i] = make_float4(0.f, 0.f, 0.f, 0.f);
        return;
    }

    if (blockIdx.x >= 512) {                       // ---- Wk transpose ----
        const int b = blockIdx.x - 512;
        const int e = b >> 6, kt = ((b >> 3) & 7) * 64, nt = (b & 7) * 64;
        const float* src = Wk + ((size_t)e * DIM + kt) * DIM + nt;
#pragma unroll
        for (int j = 0; j < 4; j++) {
            int unit = tid + 256 * j;
            int kr = unit >> 4, nc = (unit & 15) * 4;
            float4 v = *(const float4*)(src + (size_t)kr * DIM + nc);
            u.s[kr][nc + 0] = v.x; u.s[kr][nc + 1] = v.y;
            u.s[kr][nc + 2] = v.z; u.s[kr][nc + 3] = v.w;
        }
        __syncthreads();
        __half* dh = g_wk + ((size_t)e * DIM + nt) * DIM + kt;
#pragma unroll
        for (int j = 0; j < 4; j++) {
            int unit = tid + 256 * j;
            int nr = unit >> 4, kq = (unit & 15) * 4;
            __half2 p0 = __floats2half2_rn(u.s[kq + 0][nr], u.s[kq + 1][nr]);
            __half2 p1 = __floats2half2_rn(u.s[kq + 2][nr], u.s[kq + 3][nr]);
            *(uint2*)(dh + (size_t)nr * DIM + kq) =
                make_uint2(*(uint32_t*)&p0, *(uint32_t*)&p1);
        }
        return;
    }

    // ---- router + x->fp16 (4 tokens/warp, 8 lanes/token) ----
    {
        float* pr = (float*)u.w[0];
        float* pn = (float*)u.w[1];
        for (int i = tid; i < DIM * NEXP; i += 256) {
            int d = i >> 3, e = i & 7;
            pr[e * DIM + d] = Wr[i];
            pn[e * DIM + d] = Wn[i];
        }
    }
    __syncthreads();

    const int warp = tid >> 5, lane = tid & 31;
    const int grp = lane >> 3, sl = lane & 7;
    const int t = blockIdx.x * 32 + warp * 4 + grp;

    const float4* xr = (const float4*)(x + (size_t)t * DIM);
    float4 xf[16];
#pragma unroll
    for (int i = 0; i < 16; i++) xf[i] = xr[sl + 8 * i];

    {
        uint2* xo = (uint2*)(g_x + (size_t)t * DIM);
#pragma unroll
        for (int i = 0; i < 16; i++) {
            __half2 p0 = __floats2half2_rn(xf[i].x, xf[i].y);
            __half2 p1 = __floats2half2_rn(xf[i].z, xf[i].w);
            xo[sl + 8 * i] = make_uint2(*(uint32_t*)&p0, *(uint32_t*)&p1);
        }
    }

    float noisy[NEXP];
#pragma unroll
    for (int e = 0; e < NEXP; e++) {
        float ar = 0.f, an = 0.f;
#pragma unroll
        for (int i = 0; i < 16; i++) {
            float4 wr = u.w[0][e][sl + 8 * i];
            float4 wn = u.w[1][e][sl + 8 * i];
            ar = fmaf(xf[i].x, wr.x, ar); ar = fmaf(xf[i].y, wr.y, ar);
            ar = fmaf(xf[i].z, wr.z, ar); ar = fmaf(xf[i].w, wr.w, ar);
            an = fmaf(xf[i].x, wn.x, an); an = fmaf(xf[i].y, wn.y, an);
            an = fmaf(xf[i].z, wn.z, an); an = fmaf(xf[i].w, wn.w, an);
        }
#pragma unroll
        for (int o = 4; o; o >>= 1) {
            ar += __shfl_xor_sync(0xffffffffu, ar, o);
            an += __shfl_xor_sync(0xffffffffu, an, o);
        }
        float lg = ar + br[e];
        float nl = an + bn[e];
        float sp = fmaxf(nl, 0.f) + log1pf(expf(-fabsf(nl)));
        noisy[e] = lg + eps[(size_t)t * NEXP + e] * sp;
    }

    if (sl == 0) {
        int i1 = 0; float v1 = noisy[0];
#pragma unroll
        for (int e = 1; e < NEXP; e++) if (noisy[e] > v1) { v1 = noisy[e]; i1 = e; }
        int i2 = -1; float v2 = -INFINITY;
#pragma unroll
        for (int e = 0; e < NEXP; e++) if (e != i1 && noisy[e] > v2) { v2 = noisy[e]; i2 = e; }
        float ex = expf(v2 - v1);
        float inv = 1.f / (1.f + ex);
        float g1 = inv, g2 = ex * inv;

        int p1 = atomicAdd(&g_count[i1], 1);
        g_tok[i1][p1] = t; g_gate[i1][p1] = g1;
        int p2 = atomicAdd(&g_count[i2], 1);
        g_tok[i2][p2] = t; g_gate[i2][p2] = g2;
    }
}

// ---------------- persistent GEMM: dynamic ticket + cross-tile pipeline -----
#define ROW_B   144
#define MAT_B   (128 * ROW_B)            // 18432
#define STAGE_B (2 * MAT_B)              // 36864
#define GEMM_SMEM (3 * STAGE_B)          // 110592

__global__ void __launch_bounds__(256, 2) expert_gemm_mma(
    const float* __restrict__ bk, float* __restrict__ out)
{
    int off[NEXP + 1];
    off[0] = 0;
#pragma unroll
    for (int e = 0; e < NEXP; e++)
        off[e + 1] = off[e] + ((g_count[e] + BM - 1) >> 7);
    const int total = off[NEXP] * 4;

    extern __shared__ char smem[];
    __shared__ int   sTok [2][BM];
    __shared__ float sGate[2][BM];
    __shared__ int   sNext;

    const int tid = threadIdx.x, wid = tid >> 5, lane = tid & 31;
    const int warp_m = wid & 3, warp_n = wid >> 2;
    const uint32_t sb = smem_u32(smem);

    const uint32_t aLd = (uint32_t)((warp_m * 32 + (lane & 15)) * ROW_B + (lane >> 4) * 16);
    const uint32_t bLd = (uint32_t)((warp_n * 64 + ((lane >> 4) * 8) + (lane & 7)) * ROW_B
                                    + ((lane >> 3) & 1) * 16);
    uint32_t stOff[4];
#pragma unroll
    for (int j = 0; j < 4; j++) {
        int unit = tid + 256 * j;
        stOff[j] = (uint32_t)((unit >> 3) * ROW_B + (unit & 7) * 16);
    }

    auto decode = [&](int w, int& de, int& dm0, int& dnb, int& dcnt) {
        int rt = w >> 2;
        dnb = (w & 3) << 7;
        int q = 0;
#pragma unroll
        for (int u = 0; u < NEXP - 1; u++) if (rt >= off[u + 1]) q = u + 1;
        de = q;
        dm0 = (rt - off[q]) * BM;
        dcnt = g_count[q];
    };
    auto calc_offs = [&](int e_, int nb_, const int* tokArr, uint32_t* aO, uint32_t* bO) {
#pragma unroll
        for (int j = 0; j < 4; j++) {
            int unit = tid + 256 * j;
            int row = unit >> 3, seg = unit & 7;
            aO[j] = (uint32_t)(tokArr[row] * DIM + seg * 8);
            bO[j] = (uint32_t)(((e_ * DIM) + nb_ + row) * DIM + seg * 8);
        }
    };
    auto issue = [&](int slot, int k0, const uint32_t* aO, const uint32_t* bO) {
        const uint32_t base = sb + slot * STAGE_B;
#pragma unroll
        for (int j = 0; j < 4; j++) {
            cp16(base + 0 * MAT_B + stOff[j], g_x  + aO[j] + k0);
            cp16(base + 1 * MAT_B + stOff[j], g_wk + bO[j] + k0);
        }
        cp_commit();
    };

    // first tile via ticket
    if (tid == 0) sNext = atomicAdd(&g_ticket, 1);
    __syncthreads();
    int work = sNext;
    if (work >= total) return;

    int e, m0, nb, cnt;
    decode(work, e, m0, nb, cnt);
    int p = 0;
    if (tid < BM) {
        int m = m0 + tid;
        bool v = (m < cnt);
        sTok [p][tid] = v ? g_tok[e][m] : g_tok[e][m0];
        sGate[p][tid] = v ? g_gate[e][m] : 0.f;
    }
    __syncthreads();

    uint32_t aOff[4], bOff[4];
    calc_offs(e, nb, sTok[p], aOff, bOff);
    int slotBase = 0;
    issue(0, 0, aOff, bOff);
    issue(1, BK, aOff, bOff);

#pragma unroll 1
    while (true) {
        if (tid == 0) sNext = atomicAdd(&g_ticket, 1);
        __syncthreads();          // publishes sNext; guards sTok[p^1] reuse
        const int nwork = sNext;
        const bool hasNext = (nwork < total);
        int e2 = 0, m02 = 0, nb2 = 0, cnt2 = 0;
        if (hasNext) {
            decode(nwork, e2, m02, nb2, cnt2);
            if (tid < BM) {
                int m = m02 + tid;
                bool v = (m < cnt2);
                sTok [p ^ 1][tid] = v ? g_tok[e2][m] : g_tok[e2][m02];
                sGate[p ^ 1][tid] = v ? g_gate[e2][m] : 0.f;
            }
        }

        float acc[2][8][4];
#pragma unroll
        for (int i = 0; i < 2; i++)
#pragma unroll
            for (int t = 0; t < 8; t++)
#pragma unroll
                for (int q = 0; q < 4; q++) acc[i][t][q] = 0.f;

        uint32_t aOff2[4], bOff2[4];

#pragma unroll 1
        for (int st = 0; st < KSTAGES; st++) {
            if (st == KSTAGES - 1 && !hasNext) cp_wait<0>();
            else                               cp_wait<1>();
            __syncthreads();
            if (st + 2 < KSTAGES) {
                issue((slotBase + st + 2) % 3, (st + 2) * BK, aOff, bOff);
            } else if (hasNext) {
                const int nst = st + 2 - KSTAGES;     // 0 or 1
                if (nst == 0) calc_offs(e2, nb2, sTok[p ^ 1], aOff2, bOff2);
                issue((slotBase + st + 2) % 3, nst * BK, aOff2, bOff2);
            }

            const uint32_t base = sb + ((slotBase + st) % 3) * STAGE_B;
            const uint32_t aB = base + 0 * MAT_B + aLd;
            const uint32_t bB = base + 1 * MAT_B + bLd;
#pragma unroll
            for (int kk = 0; kk < 4; kk++) {
                const uint32_t ko = kk * 32;
                uint32_t aF[2][4], bF[4][4];
#pragma unroll
                for (int i = 0; i < 2; i++)
                    ldsm4(aF[i][0], aF[i][1], aF[i][2], aF[i][3], aB + i * 16 * ROW_B + ko);
#pragma unroll
                for (int q = 0; q < 4; q++)
                    ldsm4(bF[q][0], bF[q][1], bF[q][2], bF[q][3], bB + q * 16 * ROW_B + ko);
#pragma unroll
                for (int i = 0; i < 2; i++)
#pragma unroll
                    for (int q = 0; q < 4; q++)
#pragma unroll
                        for (int h = 0; h < 2; h++)
                            mma16816(acc[i][2 * q + h], aF[i], &bF[q][h * 2]);
            }
        }

        // epilogue (exactly 2 commutative adds per out element -> deterministic)
        {
            float2 bkf[8];
            const float* bkp = bk + (size_t)e * DIM + nb + warp_n * 64 + (lane & 3) * 2;
#pragma unroll
            for (int t = 0; t < 8; t++) bkf[t] = *(const float2*)(bkp + t * 8);
#pragma unroll
            for (int i = 0; i < 2; i++) {
#pragma unroll
                for (int half = 0; half < 2; half++) {
                    const int mrow = warp_m * 32 + i * 16 + half * 8 + (lane >> 2);
                    const int m = m0 + mrow;
                    if (m < cnt) {
                        const int   tok = sTok [p][mrow];
                        const float g   = sGate[p][mrow];
                        float* op = out + (size_t)tok * DIM + nb + warp_n * 64 + (lane & 3) * 2;
#pragma unroll
                        for (int t = 0; t < 8; t++)
                            redf2(op + t * 8,
                                  g * (acc[i][t][half * 2 + 0] + bkf[t].x),
                                  g * (acc[i][t][half * 2 + 1] + bkf[t].y));
                    }
                }
            }
        }

        if (!hasNext) break;
        work = nwork;
        e = e2; m0 = m02; nb = nb2; cnt = cnt2;
#pragma unroll
        for (int j = 0; j < 4; j++) { aOff[j] = aOff2[j]; bOff[j] = bOff2[j]; }
        p ^= 1;
        slotBase = (slotBase + KSTAGES) % 3;
    }
}

// ---------------- launch -----------------------------------------------------
extern "C" void kernel_launch(void* const* d_in, const int* in_sizes, int n_in,
                              void* d_out, int out_size) {
    const float* x   = (const float*)d_in[0];
    const float* eps = (const float*)d_in[1];
    const float* Wr  = (const float*)d_in[2];
    const float* br  = (const float*)d_in[3];
    const float* Wn  = (const float*)d_in[4];
    const float* bn  = (const float*)d_in[5];
    const float* Wk  = (const float*)d_in[6];
    const float* bk  = (const float*)d_in[7];
    float* out = (float*)d_out;

    cudaFuncSetAttribute(expert_gemm_mma,
                         cudaFuncAttributeMaxDynamicSharedMemorySize, GEMM_SMEM);

    init_kernel<<<1, 32>>>();
    fused_prep_router<<<1024 + (NTOK * DIM / 4) / 256, 256>>>(
        x, eps, Wr, br, Wn, bn, Wk, out);
    expert_gemm_mma<<<GEMM_GRID, 256, GEMM_SMEM>>>(bk, out);
}